// round 12
// baseline (speedup 1.0000x reference)
#include <cuda_runtime.h>
#include <cuda_bf16.h>
#include <cstdint>

#define MARGIN 0.5f
#define EPSV   1e-5f

#define N_MAX  8192
#define D_MAX  256
#define TM 128
#define TN 64

#if defined(__CUDA_ARCH__) && (__CUDA_ARCH__ == 1030) && defined(__CUDA_ARCH_FEAT_SM103_ALL)
#define HAS_TCGEN05 1
#else
#define HAS_TCGEN05 0
#endif

// ---------------------------------------------------------------------------
// Device scratch
// ---------------------------------------------------------------------------
__device__ float          g_pos[N_MAX];
__device__ float          g_neg[N_MAX];
__device__ int            g_targ[N_MAX];
__device__ __nv_bfloat16  g_featbf[N_MAX * D_MAX];
__device__ int            g_done;

// ---------------------------------------------------------------------------
// Prep: fp32->bf16 features, target->int32 (inline int64/int32 probe),
// zero accumulators + ticket.
// ---------------------------------------------------------------------------
__global__ void convert_kernel(const float* __restrict__ feat,
                               const void* __restrict__ targ, int n, int d) {
    __shared__ int s_is64;
    const int i = blockIdx.x * blockDim.x + threadIdx.x;

    const bool need_t = (blockIdx.x * blockDim.x) < n;
    if (need_t) {
        if (threadIdx.x == 0) {
            const long long* t = (const long long*)targ;
            int m = n / 2; if (m > 33) m = 33;
            bool is64 = true;
            for (int k = 1; k < m; ++k) {
                long long v = t[k];
                if (v < 0 || v >= (1LL << 30)) { is64 = false; break; }
            }
            s_is64 = is64 ? 1 : 0;
        }
        __syncthreads();
    }

    const int total4 = (n * d) >> 2;
    if (i < total4) {
        float4 v = reinterpret_cast<const float4*>(feat)[i];
        __nv_bfloat162 lo = __nv_bfloat162(__float2bfloat16(v.x), __float2bfloat16(v.y));
        __nv_bfloat162 hi = __nv_bfloat162(__float2bfloat16(v.z), __float2bfloat16(v.w));
        reinterpret_cast<__nv_bfloat162*>(g_featbf)[i * 2 + 0] = lo;
        reinterpret_cast<__nv_bfloat162*>(g_featbf)[i * 2 + 1] = hi;
    }
    if (i < n) {
        g_pos[i] = 0.0f; g_neg[i] = 0.0f;
        g_targ[i] = s_is64 ? (int)((const long long*)targ)[i]
                           : ((const int*)targ)[i];
    }
    if (i == 0) g_done = 0;
}

// ---------------------------------------------------------------------------
// PTX helpers
// ---------------------------------------------------------------------------
__device__ __forceinline__ uint32_t smem_u32(const void* p) {
    uint32_t a;
    asm("{ .reg .u64 t; cvta.to.shared.u64 t, %1; cvt.u32.u64 %0, t; }"
        : "=r"(a) : "l"(p));
    return a;
}

__device__ __forceinline__ uint32_t elect_one() {
    uint32_t pred;
    asm volatile("{\n\t.reg .pred p;\n\telect.sync _|p, 0xFFFFFFFF;\n\t"
                 "selp.b32 %0, 1, 0, p;\n\t}" : "=r"(pred));
    return pred;
}

#define MBARRIER_INIT(mbar, count) \
    asm volatile("mbarrier.init.shared.b64 [%0], %1;" \
                 :: "r"((uint32_t)(mbar)), "r"((uint32_t)(count)) : "memory")

#define MBARRIER_ARRIVE(mbar) \
    asm volatile("mbarrier.arrive.shared.b64 _, [%0];" \
                 :: "r"((uint32_t)(mbar)) : "memory")

#define MBARRIER_WAIT_PARITY(mbar, parity) do {                                   \
    uint32_t _m = (uint32_t)(mbar); uint32_t _p = (uint32_t)(parity);             \
    uint32_t _done;                                                               \
    asm volatile("{\n\t.reg .pred p;\n\t"                                         \
        "mbarrier.try_wait.parity.acquire.cta.shared::cta.b64 p, [%1], %2;\n\t"   \
        "selp.b32 %0, 1, 0, p;\n\t}" : "=r"(_done) : "r"(_m), "r"(_p) : "memory");\
    if (!_done) {                                                                 \
        asm volatile("{\n\t.reg .pred P1;\n\t"                                    \
            "WAIT_LOOP_%=:\n\t"                                                   \
            "mbarrier.try_wait.parity.acquire.cta.shared::cta.b64 P1, [%0], %1, 0x989680;\n\t" \
            "@P1 bra.uni WAIT_DONE_%=;\n\t"                                       \
            "bra.uni WAIT_LOOP_%=;\n\t"                                           \
            "WAIT_DONE_%=:\n\t}" :: "r"(_m), "r"(_p) : "memory");                 \
    }                                                                             \
} while (0)

#if HAS_TCGEN05

#define TCGEN05_ALLOC(sm_addr, nCols) \
    asm volatile("tcgen05.alloc.cta_group::1.sync.aligned.shared::cta.b32 [%0], %1;" \
                 :: "r"((uint32_t)(sm_addr)), "r"((uint32_t)(nCols)) : "memory")
#define TCGEN05_DEALLOC(tmem_addr, nCols) \
    asm volatile("tcgen05.dealloc.cta_group::1.sync.aligned.b32 %0, %1;" \
                 :: "r"(tmem_addr), "r"((uint32_t)(nCols)))
#define TCGEN05_RELINQUISH() \
    asm volatile("tcgen05.relinquish_alloc_permit.cta_group::1.sync.aligned;")
#define TCGEN05_COMMIT(mbar) \
    asm volatile("tcgen05.commit.cta_group::1.mbarrier::arrive::one.shared::cluster.b64 [%0];" \
                 :: "r"((uint32_t)(mbar)) : "memory")
#define TCGEN05_FENCE_AFTER()  asm volatile("tcgen05.fence::after_thread_sync;"  ::: "memory")
#define TCGEN05_FENCE_BEFORE() asm volatile("tcgen05.fence::before_thread_sync;" ::: "memory")
#define TCGEN05_WAIT_LD()      asm volatile("tcgen05.wait::ld.sync.aligned;"     ::: "memory")
#define TCGEN05_WAIT_ST()      asm volatile("tcgen05.wait::st.sync.aligned;"     ::: "memory")

#define TCGEN05_LD_32X32B_X32(r, tmem_addr) \
    asm volatile( \
        "tcgen05.ld.sync.aligned.32x32b.x32.b32 " \
        "{%0, %1, %2, %3, %4, %5, %6, %7, " \
        " %8, %9, %10, %11, %12, %13, %14, %15, " \
        " %16, %17, %18, %19, %20, %21, %22, %23, " \
        " %24, %25, %26, %27, %28, %29, %30, %31}, [%32];" \
        : "=r"((r)[0]),  "=r"((r)[1]),  "=r"((r)[2]),  "=r"((r)[3]), \
          "=r"((r)[4]),  "=r"((r)[5]),  "=r"((r)[6]),  "=r"((r)[7]), \
          "=r"((r)[8]),  "=r"((r)[9]),  "=r"((r)[10]), "=r"((r)[11]), \
          "=r"((r)[12]), "=r"((r)[13]), "=r"((r)[14]), "=r"((r)[15]), \
          "=r"((r)[16]), "=r"((r)[17]), "=r"((r)[18]), "=r"((r)[19]), \
          "=r"((r)[20]), "=r"((r)[21]), "=r"((r)[22]), "=r"((r)[23]), \
          "=r"((r)[24]), "=r"((r)[25]), "=r"((r)[26]), "=r"((r)[27]), \
          "=r"((r)[28]), "=r"((r)[29]), "=r"((r)[30]), "=r"((r)[31]) \
        : "r"(tmem_addr))

#define TCGEN05_ST_32X32B_X32(tmem_addr, r) \
    asm volatile( \
        "tcgen05.st.sync.aligned.32x32b.x32.b32 [%0], " \
        "{%1, %2, %3, %4, %5, %6, %7, %8, " \
        " %9, %10, %11, %12, %13, %14, %15, %16, " \
        " %17, %18, %19, %20, %21, %22, %23, %24, " \
        " %25, %26, %27, %28, %29, %30, %31, %32};" \
        :: "r"(tmem_addr), \
           "r"((r)[0]),  "r"((r)[1]),  "r"((r)[2]),  "r"((r)[3]), \
           "r"((r)[4]),  "r"((r)[5]),  "r"((r)[6]),  "r"((r)[7]), \
           "r"((r)[8]),  "r"((r)[9]),  "r"((r)[10]), "r"((r)[11]), \
           "r"((r)[12]), "r"((r)[13]), "r"((r)[14]), "r"((r)[15]), \
           "r"((r)[16]), "r"((r)[17]), "r"((r)[18]), "r"((r)[19]), \
           "r"((r)[20]), "r"((r)[21]), "r"((r)[22]), "r"((r)[23]), \
           "r"((r)[24]), "r"((r)[25]), "r"((r)[26]), "r"((r)[27]), \
           "r"((r)[28]), "r"((r)[29]), "r"((r)[30]), "r"((r)[31]) \
        : "memory")

// SW128 K-major descriptor: version=1, SBO=64, LBO=1
static constexpr uint64_t SMEM_DESC_BASE_SW128 =
    (uint64_t(2)  << 61) | (uint64_t(1) << 46) | (uint64_t(64) << 32) | (uint64_t(1) << 16);

__device__ __forceinline__ uint64_t make_desc(uint32_t addr) {
    return SMEM_DESC_BASE_SW128 | ((uint64_t)(addr >> 4) & 0x3FFF);
}

// TS-mode bf16 MMA: A in TMEM, B in SMEM
__device__ __forceinline__ void mma_f16_ts(uint32_t d_tmem, uint32_t a_tmem,
                                           uint64_t b_desc, uint32_t idesc, bool acc) {
    uint32_t en = acc ? 1u : 0u;
    asm volatile(
        "{\n\t.reg .pred p;\n\tsetp.ne.u32 p, %5, 0;\n\t"
        "tcgen05.mma.cta_group::1.kind::f16 [%0], [%1], %2, %3, {%4, %4, %4, %4}, p;\n\t}"
        :: "r"(d_tmem), "r"(a_tmem), "l"(b_desc), "r"(idesc), "r"(0u), "r"(en)
        : "memory");
}

// fp32 acc, bf16 a/b, M=128, N=64
static constexpr uint32_t MMA_IDESC =
    (1u << 4) | (1u << 7) | (1u << 10) | ((TN / 8) << 17) | ((TM / 16) << 24);

#endif  // HAS_TCGEN05

// ---------------------------------------------------------------------------
// SMEM layout (per CTA): 3 B buffers, 3 tcol, mbars
// ---------------------------------------------------------------------------
#define SMEM_B(b)     ((b) * 32768)            // 3 x 32 KB
#define SMEM_TCOL(b)  (98304 + (b) * 256)      // 3 x 256 B
#define SMEM_FULL(s)  (99072 + (s) * 8)        // 2 (MMA commit)
#define SMEM_EMPTY(s) (99088 + (s) * 8)        // 2 (epilogue done, count 128)
#define SMEM_READY(b) (99104 + (b) * 8)        // 3 (B+tcol loaded, count 128)
#define SMEM_TMEMPTR  99128
#define SMEM_TOTAL    99136

#define TMEM_COLS     256          // 2 x 64 D + 128 A
#define TMEM_D(s)     ((s) * 64)
#define TMEM_A_OFF    128

#define GRID_CTAS     296          // 2 CTAs per SM
#define NTHREADS      256

#if HAS_TCGEN05
// Load one 64-row x 256-col bf16 B tile into SW128 K-major blocked-atom
// layout (8 atom-rows; atom-col stride 8 KB). 128 threads.
__device__ __forceinline__ void load_tileB(char* smem, uint32_t dst,
                                           int gbase, int lt) {
    const uint4* src = reinterpret_cast<const uint4*>(g_featbf);
    #pragma unroll
    for (int k = 0; k < 16; ++k) {
        int idx = lt + k * 128;              // 0..2047
        int r = idx >> 5, ch = idx & 31;
        uint32_t byte = ((uint32_t)((r >> 3) + (ch >> 3) * 8) << 10)
                      + ((uint32_t)(r & 7) << 7) + ((uint32_t)(ch & 7) << 4);
        uint32_t sw = byte ^ ((byte >> 3) & 0x70);
        *reinterpret_cast<uint4*>(smem + dst + sw) =
            src[(size_t)(gbase + r) * 32 + ch];
    }
}

// Full-K (=256) TS MMA batch: 16 chained K=16 steps.
// B desc: atom-col stride 8192 B = 512 units, +2 units per K=16 step.
__device__ __forceinline__ void issue_mma_ts(uint32_t d_tmem, uint32_t a_tmem,
                                             uint32_t b_addr, uint32_t mbar) {
    uint64_t b_base = make_desc(b_addr);
    #pragma unroll
    for (int s = 0; s < 16; ++s) {
        uint64_t boff = ((uint64_t)(s >> 2) << 9) | (uint64_t)((s & 3) << 1);
        mma_f16_ts(d_tmem, a_tmem + s * 8, b_base + boff, MMA_IDESC, s > 0);
    }
    TCGEN05_COMMIT(mbar);
}
#endif

// ---------------------------------------------------------------------------
// Persistent decoupled producer/consumer sim kernel, 2 CTAs/SM.
//   warps 4-7 (producers): own loop; load B+tcol, arrive readyB,
//                          elected thread issues MMA -> commit fullD.
//   warps 0-3 (consumers): own loop; wait readyB+fullD, LDTM, masks,
//                          arrive emptyD (count 128).
// NO __syncthreads() in the tile loops — only counted mbarriers.
//
// Strict-parity audit (try_wait.parity only succeeds in the one-phase
// window): every wait below is provably checked before a second completion
// can land. The R11 deadlock was an extra producer wait on FULL for B-slot
// reuse, which COULD wrap (commits land every 2 tiles per slot). It is
// removed here because it is implied: producer(tt) waits EMPTY for
// consumer(tt-2); consumer(tt-2) passed FULL(tt-2) => MMA(tt-2) committed
// => (in-order commits) MMA(tt-3) committed => B slot tt%3 free.
// ---------------------------------------------------------------------------
__global__ __launch_bounds__(NTHREADS, 2)
void sim_tc_kernel(float* out, int n, int d, int n_new, float alpha)
{
#if HAS_TCGEN05
    extern __shared__ __align__(1024) char smem[];
    const uint32_t sb = smem_u32(smem);
    const int tid  = threadIdx.x;
    const int wid  = tid >> 5;
    const int lane = tid & 31;

    if (wid == 0) {
        TCGEN05_ALLOC(sb + SMEM_TMEMPTR, TMEM_COLS);
        TCGEN05_RELINQUISH();
    }
    if (tid == 0) {
        MBARRIER_INIT(sb + SMEM_FULL(0), 1);
        MBARRIER_INIT(sb + SMEM_FULL(1), 1);
        MBARRIER_INIT(sb + SMEM_EMPTY(0), 128);
        MBARRIER_INIT(sb + SMEM_EMPTY(1), 128);
        MBARRIER_INIT(sb + SMEM_READY(0), 128);
        MBARRIER_INIT(sb + SMEM_READY(1), 128);
        MBARRIER_INIT(sb + SMEM_READY(2), 128);
    }
    __syncthreads();

    uint32_t tmem;
    asm volatile("ld.shared.b32 %0, [%1];" : "=r"(tmem) : "r"(sb + SMEM_TMEMPTR));

    // ---- tile enumeration (TN=64 columns per tile) ---------------------------
    const int slabs_new = n_new / TM;            // 32
    const int cols_full = n / TN;                // 128
    const int cols_new  = n_new / TN;            // 64
    const int slabs_tot = n / TM;                // 64
    const int tiles_new = slabs_new * cols_full; // 4096
    const int tiles_tot = tiles_new + (slabs_tot - slabs_new) * cols_new; // 6144

    const int G = gridDim.x;
    int t   = (int)((long long)blockIdx.x       * tiles_tot / G);
    int end = (int)((long long)(blockIdx.x + 1) * tiles_tot / G);

    const bool is_loader = wid >= 4;
    const int  lt  = tid - 128;                  // loader-local tid
    const int  row = wid * 32 + lane;            // epilogue row (wid<4)

    int c = 0;                                   // global tile counter

    while (t < end) {
        // decode run: contiguous tiles sharing one row slab
        int slab, col0, slab_cols, slab_t0;
        if (t < tiles_new) {
            slab = t / cols_full; col0 = t - slab * cols_full;
            slab_cols = cols_full; slab_t0 = slab * cols_full;
        } else {
            int u = t - tiles_new;
            slab = slabs_new + u / cols_new; col0 = u % cols_new;
            slab_cols = cols_new;
            slab_t0 = tiles_new + (slab - slabs_new) * cols_new;
        }
        int run_len = slab_t0 + slab_cols - t;
        if (run_len > end - t) run_len = end - t;
        const int rowbase = slab * TM;
        const bool row_new = rowbase < n_new;

        // ---- run boundary: drain old run, upload A to TMEM -------------------
        __syncthreads();                         // all old tiles consumed
        if (!is_loader) {
            const uint4* src = reinterpret_cast<const uint4*>(g_featbf);
            const uint32_t woff = (uint32_t)wid << 21;
            #pragma unroll
            for (int q = 0; q < 4; ++q) {
                uint32_t regs[32];
                #pragma unroll
                for (int j = 0; j < 8; ++j) {
                    uint4 v = src[(size_t)(rowbase + tid) * 32 + q * 8 + j];
                    regs[j * 4 + 0] = v.x; regs[j * 4 + 1] = v.y;
                    regs[j * 4 + 2] = v.z; regs[j * 4 + 3] = v.w;
                }
                TCGEN05_ST_32X32B_X32(tmem + TMEM_A_OFF + q * 32 + woff, regs);
            }
            TCGEN05_WAIT_ST();
            TCGEN05_FENCE_BEFORE();
        }
        __syncthreads();                         // A visible to MMA issuer

        if (is_loader) {
            // ================= producer loop (no CTA syncs) ==================
            for (int i = 0; i < run_len; ++i) {
                const int tt = c + i;
                const int bslot = tt % 3;
                const int dslot = tt & 1;
                const int colbase = (col0 + i) * TN;

                // D slot + tcol + B slot free: consumer(tt-2) done.
                // (B slot freedom is implied — see header comment.)
                if (tt >= 2)
                    MBARRIER_WAIT_PARITY(sb + SMEM_EMPTY(dslot),
                                         ((tt >> 1) & 1) ^ 1);

                load_tileB(smem, SMEM_B(bslot), colbase, lt);
                if (lt < TN)
                    ((int*)(smem + SMEM_TCOL(bslot)))[lt] = g_targ[colbase + lt];
                asm volatile("fence.proxy.async.shared::cta;" ::: "memory");
                MBARRIER_ARRIVE(sb + SMEM_READY(bslot));

                if (wid == 4) {
                    if (elect_one()) {
                        // all 128 loader arrivals (completion tt/3)
                        MBARRIER_WAIT_PARITY(sb + SMEM_READY(bslot),
                                             (tt / 3) & 1);
                        TCGEN05_FENCE_AFTER();
                        issue_mma_ts(tmem + TMEM_D(dslot), tmem + TMEM_A_OFF,
                                     sb + SMEM_B(bslot), sb + SMEM_FULL(dslot));
                    }
                }
            }
        } else {
            // ================= consumer loop (no CTA syncs) ==================
            const int ti = __ldg(&g_targ[rowbase + row]);
            float p = 0.0f, ng = 0.0f;

            for (int i = 0; i < run_len; ++i) {
                const int cc = c + i;
                const int bslot = cc % 3;
                const int dslot = cc & 1;

                // tcol visible (acquire pairs with loader arrivals)
                MBARRIER_WAIT_PARITY(sb + SMEM_READY(bslot), (cc / 3) & 1);
                // D ready (completion cc>>1)
                MBARRIER_WAIT_PARITY(sb + SMEM_FULL(dslot), (cc >> 1) & 1);
                TCGEN05_FENCE_AFTER();

                const int colbase = (col0 + i) * TN;
                const bool do_pos = row_new && (colbase < n_new);
                const int* tc = (const int*)(smem + SMEM_TCOL(bslot));
                const uint32_t dbase = tmem + TMEM_D(dslot);
                uint32_t dr[32];

                // half 0
                TCGEN05_LD_32X32B_X32(dr, dbase);
                TCGEN05_WAIT_LD();
                if (do_pos) {
                    #pragma unroll
                    for (int j = 0; j < 32; ++j) {
                        const float s = __uint_as_float(dr[j]);
                        const int tj = tc[j];
                        if (ti != tj) { if (s > MARGIN) ng += s; }
                        else if (s < 1.0f - EPSV) p += 1.0f - s;
                    }
                } else {
                    #pragma unroll
                    for (int j = 0; j < 32; ++j) {
                        const float s = __uint_as_float(dr[j]);
                        if (ti != tc[j] && s > MARGIN) ng += s;
                    }
                }
                // half 1
                TCGEN05_LD_32X32B_X32(dr, dbase + 32);
                TCGEN05_WAIT_LD();
                if (do_pos) {
                    #pragma unroll
                    for (int j = 0; j < 32; ++j) {
                        const float s = __uint_as_float(dr[j]);
                        const int tj = tc[32 + j];
                        if (ti != tj) { if (s > MARGIN) ng += s; }
                        else if (s < 1.0f - EPSV) p += 1.0f - s;
                    }
                } else {
                    #pragma unroll
                    for (int j = 0; j < 32; ++j) {
                        const float s = __uint_as_float(dr[j]);
                        if (ti != tc[32 + j] && s > MARGIN) ng += s;
                    }
                }
                TCGEN05_FENCE_BEFORE();
                MBARRIER_ARRIVE(sb + SMEM_EMPTY(dslot));  // D + tcol consumed
            }

            atomicAdd(&g_neg[rowbase + row], ng);
            if (p != 0.0f) atomicAdd(&g_pos[rowbase + row], p);
        }

        c += run_len;
        t += run_len;
    }

    __syncthreads();
    if (wid == 0) TCGEN05_DEALLOC(tmem, TMEM_COLS);

    // ---- last CTA computes the final scalar ---------------------------------
    __threadfence();
    __shared__ int s_last;
    if (tid == 0)
        s_last = (atomicAdd(&g_done, 1) == gridDim.x - 1) ? 1 : 0;
    __syncthreads();
    if (s_last) {
        double* sh = reinterpret_cast<double*>(smem);
        const double a = (double)alpha;
        const double b = 1.0 - a;
        const double stale = (double)__ldcg(&g_pos[n_new - 1]);
        double s = 0.0;
        for (int i = tid; i < n; i += NTHREADS) {
            double pv = (i < n_new) ? (double)__ldcg(&g_pos[i]) : stale;
            s += a * pv + b * (double)__ldcg(&g_neg[i]);
        }
        sh[tid] = s;
        __syncthreads();
        for (int off = NTHREADS / 2; off > 0; off >>= 1) {
            if (tid < off) sh[tid] += sh[tid + off];
            __syncthreads();
        }
        if (tid == 0) out[0] = (float)(sh[0] / (double)n);
    }
#endif  // HAS_TCGEN05
}

// ---------------------------------------------------------------------------
extern "C" void kernel_launch(void* const* d_in, const int* in_sizes, int n_in,
                              void* d_out, int out_size)
{
    const float* feat = (const float*)d_in[0];
    const void*  targ = d_in[1];

    const int n     = in_sizes[1];             // 8192
    const int d     = in_sizes[0] / n;         // 256
    const int n_new = in_sizes[2];             // 4096
    const int n_old = (n_in > 3) ? in_sizes[3] : 0;
    const float alpha = (n_old != 0) ? 0.9f : 0.5f;

    cudaFuncSetAttribute(sim_tc_kernel,
                         cudaFuncAttributeMaxDynamicSharedMemorySize, SMEM_TOTAL);

    {
        int total4 = (n * d) >> 2;
        convert_kernel<<<(total4 + 255) / 256, 256>>>(feat, targ, n, d);
    }
    sim_tc_kernel<<<GRID_CTAS, NTHREADS, SMEM_TOTAL>>>((float*)d_out, n, d, n_new, alpha);
}

// round 13
// speedup vs baseline: 1.0727x; 1.0727x over previous
#include <cuda_runtime.h>
#include <cuda_bf16.h>
#include <cstdint>

#define MARGIN 0.5f
#define EPSV   1e-5f

#define N_MAX  8192
#define D_MAX  256
#define TM 128
#define TN 64

#if defined(__CUDA_ARCH__) && (__CUDA_ARCH__ == 1030) && defined(__CUDA_ARCH_FEAT_SM103_ALL)
#define HAS_TCGEN05 1
#else
#define HAS_TCGEN05 0
#endif

// ---------------------------------------------------------------------------
// Device scratch
// ---------------------------------------------------------------------------
__device__ float          g_pos[N_MAX];
__device__ float          g_neg[N_MAX];
__device__ int            g_targ[N_MAX];
__device__ __nv_bfloat16  g_featbf[N_MAX * D_MAX];
__device__ int            g_done;

// ---------------------------------------------------------------------------
// Prep: fp32->bf16 features, target->int32 (inline int64/int32 probe),
// zero accumulators + ticket.
// ---------------------------------------------------------------------------
__global__ void convert_kernel(const float* __restrict__ feat,
                               const void* __restrict__ targ, int n, int d) {
    __shared__ int s_is64;
    const int i = blockIdx.x * blockDim.x + threadIdx.x;

    const bool need_t = (blockIdx.x * blockDim.x) < n;
    if (need_t) {
        if (threadIdx.x == 0) {
            const long long* t = (const long long*)targ;
            int m = n / 2; if (m > 33) m = 33;
            bool is64 = true;
            for (int k = 1; k < m; ++k) {
                long long v = t[k];
                if (v < 0 || v >= (1LL << 30)) { is64 = false; break; }
            }
            s_is64 = is64 ? 1 : 0;
        }
        __syncthreads();
    }

    const int total4 = (n * d) >> 2;
    if (i < total4) {
        float4 v = reinterpret_cast<const float4*>(feat)[i];
        __nv_bfloat162 lo = __nv_bfloat162(__float2bfloat16(v.x), __float2bfloat16(v.y));
        __nv_bfloat162 hi = __nv_bfloat162(__float2bfloat16(v.z), __float2bfloat16(v.w));
        reinterpret_cast<__nv_bfloat162*>(g_featbf)[i * 2 + 0] = lo;
        reinterpret_cast<__nv_bfloat162*>(g_featbf)[i * 2 + 1] = hi;
    }
    if (i < n) {
        g_pos[i] = 0.0f; g_neg[i] = 0.0f;
        g_targ[i] = s_is64 ? (int)((const long long*)targ)[i]
                           : ((const int*)targ)[i];
    }
    if (i == 0) g_done = 0;
}

// ---------------------------------------------------------------------------
// PTX helpers
// ---------------------------------------------------------------------------
__device__ __forceinline__ uint32_t smem_u32(const void* p) {
    uint32_t a;
    asm("{ .reg .u64 t; cvta.to.shared.u64 t, %1; cvt.u32.u64 %0, t; }"
        : "=r"(a) : "l"(p));
    return a;
}

__device__ __forceinline__ uint32_t elect_one() {
    uint32_t pred;
    asm volatile("{\n\t.reg .pred p;\n\telect.sync _|p, 0xFFFFFFFF;\n\t"
                 "selp.b32 %0, 1, 0, p;\n\t}" : "=r"(pred));
    return pred;
}

#define MBARRIER_INIT(mbar, count) \
    asm volatile("mbarrier.init.shared.b64 [%0], %1;" \
                 :: "r"((uint32_t)(mbar)), "r"((uint32_t)(count)) : "memory")

#define MBARRIER_ARRIVE(mbar) \
    asm volatile("mbarrier.arrive.shared.b64 _, [%0];" \
                 :: "r"((uint32_t)(mbar)) : "memory")

#define MBARRIER_WAIT_PARITY(mbar, parity) do {                                   \
    uint32_t _m = (uint32_t)(mbar); uint32_t _p = (uint32_t)(parity);             \
    uint32_t _done;                                                               \
    asm volatile("{\n\t.reg .pred p;\n\t"                                         \
        "mbarrier.try_wait.parity.acquire.cta.shared::cta.b64 p, [%1], %2;\n\t"   \
        "selp.b32 %0, 1, 0, p;\n\t}" : "=r"(_done) : "r"(_m), "r"(_p) : "memory");\
    if (!_done) {                                                                 \
        asm volatile("{\n\t.reg .pred P1;\n\t"                                    \
            "WAIT_LOOP_%=:\n\t"                                                   \
            "mbarrier.try_wait.parity.acquire.cta.shared::cta.b64 P1, [%0], %1, 0x989680;\n\t" \
            "@P1 bra.uni WAIT_DONE_%=;\n\t"                                       \
            "bra.uni WAIT_LOOP_%=;\n\t"                                           \
            "WAIT_DONE_%=:\n\t}" :: "r"(_m), "r"(_p) : "memory");                 \
    }                                                                             \
} while (0)

#if HAS_TCGEN05

#define TCGEN05_ALLOC(sm_addr, nCols) \
    asm volatile("tcgen05.alloc.cta_group::1.sync.aligned.shared::cta.b32 [%0], %1;" \
                 :: "r"((uint32_t)(sm_addr)), "r"((uint32_t)(nCols)) : "memory")
#define TCGEN05_DEALLOC(tmem_addr, nCols) \
    asm volatile("tcgen05.dealloc.cta_group::1.sync.aligned.b32 %0, %1;" \
                 :: "r"(tmem_addr), "r"((uint32_t)(nCols)))
#define TCGEN05_RELINQUISH() \
    asm volatile("tcgen05.relinquish_alloc_permit.cta_group::1.sync.aligned;")
#define TCGEN05_COMMIT(mbar) \
    asm volatile("tcgen05.commit.cta_group::1.mbarrier::arrive::one.shared::cluster.b64 [%0];" \
                 :: "r"((uint32_t)(mbar)) : "memory")
#define TCGEN05_FENCE_AFTER()  asm volatile("tcgen05.fence::after_thread_sync;"  ::: "memory")
#define TCGEN05_FENCE_BEFORE() asm volatile("tcgen05.fence::before_thread_sync;" ::: "memory")
#define TCGEN05_WAIT_LD()      asm volatile("tcgen05.wait::ld.sync.aligned;"     ::: "memory")
#define TCGEN05_WAIT_ST()      asm volatile("tcgen05.wait::st.sync.aligned;"     ::: "memory")

#define TCGEN05_LD_32X32B_X32(r, tmem_addr) \
    asm volatile( \
        "tcgen05.ld.sync.aligned.32x32b.x32.b32 " \
        "{%0, %1, %2, %3, %4, %5, %6, %7, " \
        " %8, %9, %10, %11, %12, %13, %14, %15, " \
        " %16, %17, %18, %19, %20, %21, %22, %23, " \
        " %24, %25, %26, %27, %28, %29, %30, %31}, [%32];" \
        : "=r"((r)[0]),  "=r"((r)[1]),  "=r"((r)[2]),  "=r"((r)[3]), \
          "=r"((r)[4]),  "=r"((r)[5]),  "=r"((r)[6]),  "=r"((r)[7]), \
          "=r"((r)[8]),  "=r"((r)[9]),  "=r"((r)[10]), "=r"((r)[11]), \
          "=r"((r)[12]), "=r"((r)[13]), "=r"((r)[14]), "=r"((r)[15]), \
          "=r"((r)[16]), "=r"((r)[17]), "=r"((r)[18]), "=r"((r)[19]), \
          "=r"((r)[20]), "=r"((r)[21]), "=r"((r)[22]), "=r"((r)[23]), \
          "=r"((r)[24]), "=r"((r)[25]), "=r"((r)[26]), "=r"((r)[27]), \
          "=r"((r)[28]), "=r"((r)[29]), "=r"((r)[30]), "=r"((r)[31]) \
        : "r"(tmem_addr))

#define TCGEN05_ST_32X32B_X32(tmem_addr, r) \
    asm volatile( \
        "tcgen05.st.sync.aligned.32x32b.x32.b32 [%0], " \
        "{%1, %2, %3, %4, %5, %6, %7, %8, " \
        " %9, %10, %11, %12, %13, %14, %15, %16, " \
        " %17, %18, %19, %20, %21, %22, %23, %24, " \
        " %25, %26, %27, %28, %29, %30, %31, %32};" \
        :: "r"(tmem_addr), \
           "r"((r)[0]),  "r"((r)[1]),  "r"((r)[2]),  "r"((r)[3]), \
           "r"((r)[4]),  "r"((r)[5]),  "r"((r)[6]),  "r"((r)[7]), \
           "r"((r)[8]),  "r"((r)[9]),  "r"((r)[10]), "r"((r)[11]), \
           "r"((r)[12]), "r"((r)[13]), "r"((r)[14]), "r"((r)[15]), \
           "r"((r)[16]), "r"((r)[17]), "r"((r)[18]), "r"((r)[19]), \
           "r"((r)[20]), "r"((r)[21]), "r"((r)[22]), "r"((r)[23]), \
           "r"((r)[24]), "r"((r)[25]), "r"((r)[26]), "r"((r)[27]), \
           "r"((r)[28]), "r"((r)[29]), "r"((r)[30]), "r"((r)[31]) \
        : "memory")

// SW128 K-major descriptor: version=1, SBO=64, LBO=1
static constexpr uint64_t SMEM_DESC_BASE_SW128 =
    (uint64_t(2)  << 61) | (uint64_t(1) << 46) | (uint64_t(64) << 32) | (uint64_t(1) << 16);

__device__ __forceinline__ uint64_t make_desc(uint32_t addr) {
    return SMEM_DESC_BASE_SW128 | ((uint64_t)(addr >> 4) & 0x3FFF);
}

// TS-mode bf16 MMA: A in TMEM, B in SMEM
__device__ __forceinline__ void mma_f16_ts(uint32_t d_tmem, uint32_t a_tmem,
                                           uint64_t b_desc, uint32_t idesc, bool acc) {
    uint32_t en = acc ? 1u : 0u;
    asm volatile(
        "{\n\t.reg .pred p;\n\tsetp.ne.u32 p, %5, 0;\n\t"
        "tcgen05.mma.cta_group::1.kind::f16 [%0], [%1], %2, %3, {%4, %4, %4, %4}, p;\n\t}"
        :: "r"(d_tmem), "r"(a_tmem), "l"(b_desc), "r"(idesc), "r"(0u), "r"(en)
        : "memory");
}

// fp32 acc, bf16 a/b, M=128, N=64
static constexpr uint32_t MMA_IDESC =
    (1u << 4) | (1u << 7) | (1u << 10) | ((TN / 8) << 17) | ((TM / 16) << 24);

#endif  // HAS_TCGEN05

// ---------------------------------------------------------------------------
// SMEM layout (per CTA): 4 B buffers, 4 tcol, 4x mbar triples
// ---------------------------------------------------------------------------
#define SMEM_B(b)     ((b) * 32768)            // 4 x 32 KB
#define SMEM_TCOL(b)  (131072 + (b) * 256)     // 4 x 256 B
#define SMEM_FULL(s)  (132096 + (s) * 8)       // 4 (MMA commit, count 1)
#define SMEM_EMPTY(s) (132128 + (s) * 8)       // 4 (epilogue done, count 256)
#define SMEM_READY(s) (132160 + (s) * 8)       // 4 (B+tcol loaded, count 128)
#define SMEM_TMEMPTR  132192
#define SMEM_TOTAL    132224

#define TMEM_COLS     512          // 4 x 64 D + 128 A
#define TMEM_D(s)     ((s) * 64)
#define TMEM_A_OFF    256

#define GRID_CTAS     148
#define NTHREADS      416          // 8 epilogue + 4 loader + 1 issuer warps

#if HAS_TCGEN05
// Load one 64-row x 256-col bf16 B tile into SW128 K-major blocked-atom
// layout (8 atom-rows; atom-col stride 8 KB). 128 threads.
__device__ __forceinline__ void load_tileB(char* smem, uint32_t dst,
                                           int gbase, int lt) {
    const uint4* src = reinterpret_cast<const uint4*>(g_featbf);
    #pragma unroll
    for (int k = 0; k < 16; ++k) {
        int idx = lt + k * 128;              // 0..2047
        int r = idx >> 5, ch = idx & 31;
        uint32_t byte = ((uint32_t)((r >> 3) + (ch >> 3) * 8) << 10)
                      + ((uint32_t)(r & 7) << 7) + ((uint32_t)(ch & 7) << 4);
        uint32_t sw = byte ^ ((byte >> 3) & 0x70);
        *reinterpret_cast<uint4*>(smem + dst + sw) =
            src[(size_t)(gbase + r) * 32 + ch];
    }
}

// Full-K (=256) TS MMA batch: 16 chained K=16 steps.
// B desc: atom-col stride 8192 B = 512 units, +2 units per K=16 step.
__device__ __forceinline__ void issue_mma_ts(uint32_t d_tmem, uint32_t a_tmem,
                                             uint32_t b_addr, uint32_t mbar) {
    uint64_t b_base = make_desc(b_addr);
    #pragma unroll
    for (int s = 0; s < 16; ++s) {
        uint64_t boff = ((uint64_t)(s >> 2) << 9) | (uint64_t)((s & 3) << 1);
        mma_f16_ts(d_tmem, a_tmem + s * 8, b_base + boff, MMA_IDESC, s > 0);
    }
    TCGEN05_COMMIT(mbar);
}
#endif

// ---------------------------------------------------------------------------
// Persistent depth-4 pipeline with a DEDICATED MMA issuer warp. 1 CTA/SM.
//   warps 0-7  (consumers): rows (w&3)*32+lane, cols (w>>2)*32..+31;
//                           wait READY+FULL, 1x LDTM x32, masks, arrive EMPTY.
//   warps 8-11 (producers): load B(tt)+tcol(tt) after EMPTY(tt-4); arrive READY.
//   warp  12   (issuer):    wait READY(tt), issue 16 MMAs, commit FULL(tt).
// Slots = tt & 3; phase parity = (tt >> 2) & 1 (global tile counter).
// NO __syncthreads() inside tile loops; runs are drained at slab boundaries.
// ---------------------------------------------------------------------------
__global__ __launch_bounds__(NTHREADS, 1)
void sim_tc_kernel(float* out, int n, int d, int n_new, float alpha)
{
#if HAS_TCGEN05
    extern __shared__ __align__(1024) char smem[];
    const uint32_t sb = smem_u32(smem);
    const int tid  = threadIdx.x;
    const int wid  = tid >> 5;
    const int lane = tid & 31;

    if (wid == 0) {
        TCGEN05_ALLOC(sb + SMEM_TMEMPTR, TMEM_COLS);
        TCGEN05_RELINQUISH();
    }
    if (tid == 0) {
        #pragma unroll
        for (int s = 0; s < 4; ++s) {
            MBARRIER_INIT(sb + SMEM_FULL(s), 1);
            MBARRIER_INIT(sb + SMEM_EMPTY(s), 256);
            MBARRIER_INIT(sb + SMEM_READY(s), 128);
        }
    }
    __syncthreads();

    uint32_t tmem;
    asm volatile("ld.shared.b32 %0, [%1];" : "=r"(tmem) : "r"(sb + SMEM_TMEMPTR));

    // ---- tile enumeration (TN=64 columns per tile) ---------------------------
    const int slabs_new = n_new / TM;            // 32
    const int cols_full = n / TN;                // 128
    const int cols_new  = n_new / TN;            // 64
    const int slabs_tot = n / TM;                // 64
    const int tiles_new = slabs_new * cols_full; // 4096
    const int tiles_tot = tiles_new + (slabs_tot - slabs_new) * cols_new; // 6144

    const int G = gridDim.x;
    int t   = (int)((long long)blockIdx.x       * tiles_tot / G);
    int end = (int)((long long)(blockIdx.x + 1) * tiles_tot / G);

    const int role = (wid < 8) ? 0 : (wid < 12 ? 1 : 2);   // 0=cons,1=prod,2=issuer
    const int lt   = tid - 256;                  // producer-local tid (0..127)
    const int row  = (wid & 3) * 32 + lane;      // consumer row
    const int cblk = (wid >> 2) * 32;            // consumer 32-col block (wid<8)

    int c = 0;                                   // global tile counter

    while (t < end) {
        // decode run: contiguous tiles sharing one row slab
        int slab, col0, slab_cols, slab_t0;
        if (t < tiles_new) {
            slab = t / cols_full; col0 = t - slab * cols_full;
            slab_cols = cols_full; slab_t0 = slab * cols_full;
        } else {
            int u = t - tiles_new;
            slab = slabs_new + u / cols_new; col0 = u % cols_new;
            slab_cols = cols_new;
            slab_t0 = tiles_new + (slab - slabs_new) * cols_new;
        }
        int run_len = slab_t0 + slab_cols - t;
        if (run_len > end - t) run_len = end - t;
        const int rowbase = slab * TM;
        const bool row_new = rowbase < n_new;

        // ---- run boundary: drain, upload A slab to TMEM ----------------------
        __syncthreads();
        if (wid < 4) {                           // threads 0..127, row = tid
            const uint4* src = reinterpret_cast<const uint4*>(g_featbf);
            const uint32_t woff = (uint32_t)wid << 21;
            #pragma unroll
            for (int q = 0; q < 4; ++q) {
                uint32_t regs[32];
                #pragma unroll
                for (int j = 0; j < 8; ++j) {
                    uint4 v = src[(size_t)(rowbase + tid) * 32 + q * 8 + j];
                    regs[j * 4 + 0] = v.x; regs[j * 4 + 1] = v.y;
                    regs[j * 4 + 2] = v.z; regs[j * 4 + 3] = v.w;
                }
                TCGEN05_ST_32X32B_X32(tmem + TMEM_A_OFF + q * 32 + woff, regs);
            }
            TCGEN05_WAIT_ST();
            TCGEN05_FENCE_BEFORE();
        }
        __syncthreads();                         // A visible before any MMA

        if (role == 1) {
            // ==================== producer loop ====================
            for (int i = 0; i < run_len; ++i) {
                const int tt = c + i;
                const int s  = tt & 3;
                const int colbase = (col0 + i) * TN;

                // slot free: consumer(tt-4) done (also frees B via FULL chain)
                if (tt >= 4)
                    MBARRIER_WAIT_PARITY(sb + SMEM_EMPTY(s),
                                         ((tt >> 2) & 1) ^ 1);

                load_tileB(smem, SMEM_B(s), colbase, lt);
                if (lt < TN)
                    ((int*)(smem + SMEM_TCOL(s)))[lt] = g_targ[colbase + lt];
                asm volatile("fence.proxy.async.shared::cta;" ::: "memory");
                MBARRIER_ARRIVE(sb + SMEM_READY(s));
            }
        } else if (role == 2) {
            // ==================== issuer loop (dedicated warp) ====================
            TCGEN05_FENCE_AFTER();
            for (int i = 0; i < run_len; ++i) {
                const int tt = c + i;
                const int s  = tt & 3;
                MBARRIER_WAIT_PARITY(sb + SMEM_READY(s), (tt >> 2) & 1);
                if (elect_one()) {
                    issue_mma_ts(tmem + TMEM_D(s), tmem + TMEM_A_OFF,
                                 sb + SMEM_B(s), sb + SMEM_FULL(s));
                }
            }
        } else {
            // ==================== consumer loop ====================
            const int ti = __ldg(&g_targ[rowbase + row]);
            float p = 0.0f, ng = 0.0f;

            for (int i = 0; i < run_len; ++i) {
                const int cc = c + i;
                const int s  = cc & 3;

                MBARRIER_WAIT_PARITY(sb + SMEM_READY(s), (cc >> 2) & 1); // tcol
                MBARRIER_WAIT_PARITY(sb + SMEM_FULL(s),  (cc >> 2) & 1); // D
                TCGEN05_FENCE_AFTER();

                const int colbase = (col0 + i) * TN;
                const bool do_pos = row_new && (colbase < n_new);
                const int* tc = (const int*)(smem + SMEM_TCOL(s)) + cblk;
                uint32_t dr[32];
                TCGEN05_LD_32X32B_X32(dr, tmem + TMEM_D(s) + cblk);
                TCGEN05_WAIT_LD();

                if (do_pos) {
                    #pragma unroll
                    for (int j = 0; j < 32; ++j) {
                        const float sv = __uint_as_float(dr[j]);
                        const int tj = tc[j];
                        if (ti != tj) { if (sv > MARGIN) ng += sv; }
                        else if (sv < 1.0f - EPSV) p += 1.0f - sv;
                    }
                } else {
                    #pragma unroll
                    for (int j = 0; j < 32; ++j) {
                        const float sv = __uint_as_float(dr[j]);
                        if (ti != tc[j] && sv > MARGIN) ng += sv;
                    }
                }
                TCGEN05_FENCE_BEFORE();
                MBARRIER_ARRIVE(sb + SMEM_EMPTY(s));   // slot consumed
            }

            atomicAdd(&g_neg[rowbase + row], ng);
            if (p != 0.0f) atomicAdd(&g_pos[rowbase + row], p);
        }

        c += run_len;
        t += run_len;
    }

    __syncthreads();
    if (wid == 0) TCGEN05_DEALLOC(tmem, TMEM_COLS);

    // ---- last CTA computes the final scalar ---------------------------------
    __threadfence();
    __shared__ int s_last;
    if (tid == 0)
        s_last = (atomicAdd(&g_done, 1) == gridDim.x - 1) ? 1 : 0;
    __syncthreads();
    if (s_last) {
        double* sh = reinterpret_cast<double*>(smem);
        const double a = (double)alpha;
        const double b = 1.0 - a;
        const double stale = (double)__ldcg(&g_pos[n_new - 1]);
        double s = 0.0;
        for (int i = tid; i < n; i += NTHREADS) {
            double pv = (i < n_new) ? (double)__ldcg(&g_pos[i]) : stale;
            s += a * pv + b * (double)__ldcg(&g_neg[i]);
        }
        sh[tid] = s;
        __syncthreads();
        for (int off = 256; off > 0; off >>= 1) {
            if (tid < off && tid + off < NTHREADS) sh[tid] += sh[tid + off];
            __syncthreads();
        }
        if (tid == 0) out[0] = (float)(sh[0] / (double)n);
    }
#endif  // HAS_TCGEN05
}

// ---------------------------------------------------------------------------
extern "C" void kernel_launch(void* const* d_in, const int* in_sizes, int n_in,
                              void* d_out, int out_size)
{
    const float* feat = (const float*)d_in[0];
    const void*  targ = d_in[1];

    const int n     = in_sizes[1];             // 8192
    const int d     = in_sizes[0] / n;         // 256
    const int n_new = in_sizes[2];             // 4096
    const int n_old = (n_in > 3) ? in_sizes[3] : 0;
    const float alpha = (n_old != 0) ? 0.9f : 0.5f;

    cudaFuncSetAttribute(sim_tc_kernel,
                         cudaFuncAttributeMaxDynamicSharedMemorySize, SMEM_TOTAL);

    {
        int total4 = (n * d) >> 2;
        convert_kernel<<<(total4 + 255) / 256, 256>>>(feat, targ, n, d);
    }
    sim_tc_kernel<<<GRID_CTAS, NTHREADS, SMEM_TOTAL>>>((float*)d_out, n, d, n_new, alpha);
}

// round 14
// speedup vs baseline: 1.0979x; 1.0235x over previous
#include <cuda_runtime.h>
#include <cuda_bf16.h>
#include <cstdint>

#define MARGIN 0.5f
#define EPSV   1e-5f

#define N_MAX  8192
#define D_MAX  256
#define TM 128
#define TN 64

#if defined(__CUDA_ARCH__) && (__CUDA_ARCH__ == 1030) && defined(__CUDA_ARCH_FEAT_SM103_ALL)
#define HAS_TCGEN05 1
#else
#define HAS_TCGEN05 0
#endif

// ---------------------------------------------------------------------------
// Device scratch
// ---------------------------------------------------------------------------
__device__ float          g_pos[N_MAX];
__device__ float          g_neg[N_MAX];
__device__ int            g_targ[N_MAX];
__device__ __nv_bfloat16  g_featbf[N_MAX * D_MAX];
__device__ int            g_done;

// ---------------------------------------------------------------------------
// Prep: fp32->bf16 features, target->int32 (inline int64/int32 probe),
// zero accumulators + ticket.
// ---------------------------------------------------------------------------
__global__ void convert_kernel(const float* __restrict__ feat,
                               const void* __restrict__ targ, int n, int d) {
    __shared__ int s_is64;
    const int i = blockIdx.x * blockDim.x + threadIdx.x;

    const bool need_t = (blockIdx.x * blockDim.x) < n;
    if (need_t) {
        if (threadIdx.x == 0) {
            const long long* t = (const long long*)targ;
            int m = n / 2; if (m > 33) m = 33;
            bool is64 = true;
            for (int k = 1; k < m; ++k) {
                long long v = t[k];
                if (v < 0 || v >= (1LL << 30)) { is64 = false; break; }
            }
            s_is64 = is64 ? 1 : 0;
        }
        __syncthreads();
    }

    const int total4 = (n * d) >> 2;
    if (i < total4) {
        float4 v = reinterpret_cast<const float4*>(feat)[i];
        __nv_bfloat162 lo = __nv_bfloat162(__float2bfloat16(v.x), __float2bfloat16(v.y));
        __nv_bfloat162 hi = __nv_bfloat162(__float2bfloat16(v.z), __float2bfloat16(v.w));
        reinterpret_cast<__nv_bfloat162*>(g_featbf)[i * 2 + 0] = lo;
        reinterpret_cast<__nv_bfloat162*>(g_featbf)[i * 2 + 1] = hi;
    }
    if (i < n) {
        g_pos[i] = 0.0f; g_neg[i] = 0.0f;
        g_targ[i] = s_is64 ? (int)((const long long*)targ)[i]
                           : ((const int*)targ)[i];
    }
    if (i == 0) g_done = 0;
}

// ---------------------------------------------------------------------------
// PTX helpers
// ---------------------------------------------------------------------------
__device__ __forceinline__ uint32_t smem_u32(const void* p) {
    uint32_t a;
    asm("{ .reg .u64 t; cvta.to.shared.u64 t, %1; cvt.u32.u64 %0, t; }"
        : "=r"(a) : "l"(p));
    return a;
}

__device__ __forceinline__ uint32_t elect_one() {
    uint32_t pred;
    asm volatile("{\n\t.reg .pred p;\n\telect.sync _|p, 0xFFFFFFFF;\n\t"
                 "selp.b32 %0, 1, 0, p;\n\t}" : "=r"(pred));
    return pred;
}

#define MBARRIER_INIT(mbar, count) \
    asm volatile("mbarrier.init.shared.b64 [%0], %1;" \
                 :: "r"((uint32_t)(mbar)), "r"((uint32_t)(count)) : "memory")

#define MBARRIER_ARRIVE(mbar) \
    asm volatile("mbarrier.arrive.shared.b64 _, [%0];" \
                 :: "r"((uint32_t)(mbar)) : "memory")

#define MBARRIER_WAIT_PARITY(mbar, parity) do {                                   \
    uint32_t _m = (uint32_t)(mbar); uint32_t _p = (uint32_t)(parity);             \
    uint32_t _done;                                                               \
    asm volatile("{\n\t.reg .pred p;\n\t"                                         \
        "mbarrier.try_wait.parity.acquire.cta.shared::cta.b64 p, [%1], %2;\n\t"   \
        "selp.b32 %0, 1, 0, p;\n\t}" : "=r"(_done) : "r"(_m), "r"(_p) : "memory");\
    if (!_done) {                                                                 \
        asm volatile("{\n\t.reg .pred P1;\n\t"                                    \
            "WAIT_LOOP_%=:\n\t"                                                   \
            "mbarrier.try_wait.parity.acquire.cta.shared::cta.b64 P1, [%0], %1, 0x989680;\n\t" \
            "@P1 bra.uni WAIT_DONE_%=;\n\t"                                       \
            "bra.uni WAIT_LOOP_%=;\n\t"                                           \
            "WAIT_DONE_%=:\n\t}" :: "r"(_m), "r"(_p) : "memory");                 \
    }                                                                             \
} while (0)

#if HAS_TCGEN05

#define TCGEN05_ALLOC(sm_addr, nCols) \
    asm volatile("tcgen05.alloc.cta_group::1.sync.aligned.shared::cta.b32 [%0], %1;" \
                 :: "r"((uint32_t)(sm_addr)), "r"((uint32_t)(nCols)) : "memory")
#define TCGEN05_DEALLOC(tmem_addr, nCols) \
    asm volatile("tcgen05.dealloc.cta_group::1.sync.aligned.b32 %0, %1;" \
                 :: "r"(tmem_addr), "r"((uint32_t)(nCols)))
#define TCGEN05_RELINQUISH() \
    asm volatile("tcgen05.relinquish_alloc_permit.cta_group::1.sync.aligned;")
#define TCGEN05_COMMIT(mbar) \
    asm volatile("tcgen05.commit.cta_group::1.mbarrier::arrive::one.shared::cluster.b64 [%0];" \
                 :: "r"((uint32_t)(mbar)) : "memory")
#define TCGEN05_FENCE_AFTER()  asm volatile("tcgen05.fence::after_thread_sync;"  ::: "memory")
#define TCGEN05_FENCE_BEFORE() asm volatile("tcgen05.fence::before_thread_sync;" ::: "memory")
#define TCGEN05_WAIT_LD()      asm volatile("tcgen05.wait::ld.sync.aligned;"     ::: "memory")

#define TCGEN05_LD_32X32B_X32(r, tmem_addr) \
    asm volatile( \
        "tcgen05.ld.sync.aligned.32x32b.x32.b32 " \
        "{%0, %1, %2, %3, %4, %5, %6, %7, " \
        " %8, %9, %10, %11, %12, %13, %14, %15, " \
        " %16, %17, %18, %19, %20, %21, %22, %23, " \
        " %24, %25, %26, %27, %28, %29, %30, %31}, [%32];" \
        : "=r"((r)[0]),  "=r"((r)[1]),  "=r"((r)[2]),  "=r"((r)[3]), \
          "=r"((r)[4]),  "=r"((r)[5]),  "=r"((r)[6]),  "=r"((r)[7]), \
          "=r"((r)[8]),  "=r"((r)[9]),  "=r"((r)[10]), "=r"((r)[11]), \
          "=r"((r)[12]), "=r"((r)[13]), "=r"((r)[14]), "=r"((r)[15]), \
          "=r"((r)[16]), "=r"((r)[17]), "=r"((r)[18]), "=r"((r)[19]), \
          "=r"((r)[20]), "=r"((r)[21]), "=r"((r)[22]), "=r"((r)[23]), \
          "=r"((r)[24]), "=r"((r)[25]), "=r"((r)[26]), "=r"((r)[27]), \
          "=r"((r)[28]), "=r"((r)[29]), "=r"((r)[30]), "=r"((r)[31]) \
        : "r"(tmem_addr))

// SW128 K-major descriptor: version=1, SBO=64, LBO=1
static constexpr uint64_t SMEM_DESC_BASE_SW128 =
    (uint64_t(2)  << 61) | (uint64_t(1) << 46) | (uint64_t(64) << 32) | (uint64_t(1) << 16);

__device__ __forceinline__ uint64_t make_desc(uint32_t addr) {
    return SMEM_DESC_BASE_SW128 | ((uint64_t)(addr >> 4) & 0x3FFF);
}

// SS-mode bf16 MMA: A in SMEM, B in SMEM (keeps the TMEM read port free
// for the epilogue's LDTM — the R14 theory).
__device__ __forceinline__ void mma_f16_ss(uint32_t d_tmem, uint64_t a_desc,
                                           uint64_t b_desc, uint32_t idesc, bool acc) {
    uint32_t en = acc ? 1u : 0u;
    asm volatile(
        "{\n\t.reg .pred p;\n\tsetp.ne.u32 p, %5, 0;\n\t"
        "tcgen05.mma.cta_group::1.kind::f16 [%0], %1, %2, %3, {%4, %4, %4, %4}, p;\n\t}"
        :: "r"(d_tmem), "l"(a_desc), "l"(b_desc), "r"(idesc), "r"(0u), "r"(en)
        : "memory");
}

// fp32 acc, bf16 a/b, M=128, N=64
static constexpr uint32_t MMA_IDESC =
    (1u << 4) | (1u << 7) | (1u << 10) | ((TN / 8) << 17) | ((TM / 16) << 24);

#endif  // HAS_TCGEN05

// ---------------------------------------------------------------------------
// SMEM layout (per CTA): A tile (64 KB) + 4 B buffers + 4 tcol + mbars
// ---------------------------------------------------------------------------
#define SMEM_A        0                        // 64 KB (128 rows x 256 bf16)
#define SMEM_B(b)     (65536 + (b) * 32768)    // 4 x 32 KB
#define SMEM_TCOL(b)  (196608 + (b) * 256)     // 4 x 256 B
#define SMEM_FULL(s)  (197632 + (s) * 8)       // 4 (MMA commit, count 1)
#define SMEM_EMPTY(s) (197664 + (s) * 8)       // 4 (epilogue done, count 256)
#define SMEM_READY(s) (197696 + (s) * 8)       // 4 (B+tcol loaded, count 128)
#define SMEM_TMEMPTR  197728
#define SMEM_TOTAL    197760

#define TMEM_COLS     256          // 4 x 64 D (A no longer in TMEM)
#define TMEM_D(s)     ((s) * 64)

#define GRID_CTAS     148
#define NTHREADS      416          // 8 epilogue + 4 loader + 1 issuer warps

#if HAS_TCGEN05
// Load one 64-row x 256-col bf16 B tile into SW128 K-major blocked-atom
// layout (8 atom-rows; atom-col stride 8 KB). 128 threads.
__device__ __forceinline__ void load_tileB(char* smem, uint32_t dst,
                                           int gbase, int lt) {
    const uint4* src = reinterpret_cast<const uint4*>(g_featbf);
    #pragma unroll
    for (int k = 0; k < 16; ++k) {
        int idx = lt + k * 128;              // 0..2047
        int r = idx >> 5, ch = idx & 31;
        uint32_t byte = ((uint32_t)((r >> 3) + (ch >> 3) * 8) << 10)
                      + ((uint32_t)(r & 7) << 7) + ((uint32_t)(ch & 7) << 4);
        uint32_t sw = byte ^ ((byte >> 3) & 0x70);
        *reinterpret_cast<uint4*>(smem + dst + sw) =
            src[(size_t)(gbase + r) * 32 + ch];
    }
}

// Load the 128-row x 256-col A tile into SW128 K-major blocked-atom layout
// (16 atom-rows; atom-col stride 16 KB). NT cooperating threads.
__device__ __forceinline__ void load_tileA(char* smem, int gbase, int tid, int nt) {
    const uint4* src = reinterpret_cast<const uint4*>(g_featbf);
    for (int idx = tid; idx < 4096; idx += nt) {
        int r = idx >> 5, ch = idx & 31;
        uint32_t byte = ((uint32_t)((r >> 3) + (ch >> 3) * 16) << 10)
                      + ((uint32_t)(r & 7) << 7) + ((uint32_t)(ch & 7) << 4);
        uint32_t sw = byte ^ ((byte >> 3) & 0x70);
        *reinterpret_cast<uint4*>(smem + SMEM_A + sw) =
            src[(size_t)(gbase + r) * 32 + ch];
    }
}

// Full-K (=256) SS MMA batch: 16 chained K=16 steps.
// A desc: atom-col stride 16 KB = 1024 units; B: 8 KB = 512 units; +2/step.
__device__ __forceinline__ void issue_mma_ss(uint32_t d_tmem, uint32_t a_addr,
                                             uint32_t b_addr, uint32_t mbar) {
    uint64_t a_base = make_desc(a_addr);
    uint64_t b_base = make_desc(b_addr);
    #pragma unroll
    for (int s = 0; s < 16; ++s) {
        uint64_t aoff = ((uint64_t)(s >> 2) << 10) | (uint64_t)((s & 3) << 1);
        uint64_t boff = ((uint64_t)(s >> 2) << 9)  | (uint64_t)((s & 3) << 1);
        mma_f16_ss(d_tmem, a_base + aoff, b_base + boff, MMA_IDESC, s > 0);
    }
    TCGEN05_COMMIT(mbar);
}
#endif

// ---------------------------------------------------------------------------
// Persistent depth-4 pipeline, dedicated issuer warp, SS-mode MMA. 1 CTA/SM.
//   warps 0-7  (consumers): rows (w&3)*32+lane, cols (w>>2)*32..+31;
//                           wait READY+FULL, 1x LDTM x32, masks, arrive EMPTY.
//   warps 8-11 (producers): load B(tt)+tcol(tt) after EMPTY(tt-4); arrive READY.
//   warp  12   (issuer):    wait READY(tt), issue 16 SS MMAs, commit FULL(tt).
// Slots = tt & 3; phase parity = (tt >> 2) & 1 (global tile counter).
// ---------------------------------------------------------------------------
__global__ __launch_bounds__(NTHREADS, 1)
void sim_tc_kernel(float* out, int n, int d, int n_new, float alpha)
{
#if HAS_TCGEN05
    extern __shared__ __align__(1024) char smem[];
    const uint32_t sb = smem_u32(smem);
    const int tid  = threadIdx.x;
    const int wid  = tid >> 5;
    const int lane = tid & 31;

    if (wid == 0) {
        TCGEN05_ALLOC(sb + SMEM_TMEMPTR, TMEM_COLS);
        TCGEN05_RELINQUISH();
    }
    if (tid == 0) {
        #pragma unroll
        for (int s = 0; s < 4; ++s) {
            MBARRIER_INIT(sb + SMEM_FULL(s), 1);
            MBARRIER_INIT(sb + SMEM_EMPTY(s), 256);
            MBARRIER_INIT(sb + SMEM_READY(s), 128);
        }
    }
    __syncthreads();

    uint32_t tmem;
    asm volatile("ld.shared.b32 %0, [%1];" : "=r"(tmem) : "r"(sb + SMEM_TMEMPTR));

    // ---- tile enumeration (TN=64 columns per tile) ---------------------------
    const int slabs_new = n_new / TM;            // 32
    const int cols_full = n / TN;                // 128
    const int cols_new  = n_new / TN;            // 64
    const int slabs_tot = n / TM;                // 64
    const int tiles_new = slabs_new * cols_full; // 4096
    const int tiles_tot = tiles_new + (slabs_tot - slabs_new) * cols_new; // 6144

    const int G = gridDim.x;
    int t   = (int)((long long)blockIdx.x       * tiles_tot / G);
    int end = (int)((long long)(blockIdx.x + 1) * tiles_tot / G);

    const int role = (wid < 8) ? 0 : (wid < 12 ? 1 : 2);   // 0=cons,1=prod,2=issuer
    const int lt   = tid - 256;                  // producer-local tid (0..127)
    const int row  = (wid & 3) * 32 + lane;      // consumer row
    const int cblk = (wid >> 2) * 32;            // consumer 32-col block (wid<8)

    int c = 0;                                   // global tile counter

    while (t < end) {
        // decode run: contiguous tiles sharing one row slab
        int slab, col0, slab_cols, slab_t0;
        if (t < tiles_new) {
            slab = t / cols_full; col0 = t - slab * cols_full;
            slab_cols = cols_full; slab_t0 = slab * cols_full;
        } else {
            int u = t - tiles_new;
            slab = slabs_new + u / cols_new; col0 = u % cols_new;
            slab_cols = cols_new;
            slab_t0 = tiles_new + (slab - slabs_new) * cols_new;
        }
        int run_len = slab_t0 + slab_cols - t;
        if (run_len > end - t) run_len = end - t;
        const int rowbase = slab * TM;
        const bool row_new = rowbase < n_new;

        // ---- run boundary: drain, load A slab into SMEM ----------------------
        // Safe to overwrite A: every MMA of the previous run had its FULL
        // commit observed by a consumer before this barrier.
        __syncthreads();
        load_tileA(smem, rowbase, tid, NTHREADS);
        asm volatile("fence.proxy.async.shared::cta;" ::: "memory");
        __syncthreads();                         // A visible before any MMA

        if (role == 1) {
            // ==================== producer loop ====================
            for (int i = 0; i < run_len; ++i) {
                const int tt = c + i;
                const int s  = tt & 3;
                const int colbase = (col0 + i) * TN;

                // slot free: consumer(tt-4) done (B freedom via FULL chain)
                if (tt >= 4)
                    MBARRIER_WAIT_PARITY(sb + SMEM_EMPTY(s),
                                         ((tt >> 2) & 1) ^ 1);

                load_tileB(smem, SMEM_B(s), colbase, lt);
                if (lt < TN)
                    ((int*)(smem + SMEM_TCOL(s)))[lt] = g_targ[colbase + lt];
                asm volatile("fence.proxy.async.shared::cta;" ::: "memory");
                MBARRIER_ARRIVE(sb + SMEM_READY(s));
            }
        } else if (role == 2) {
            // ==================== issuer loop (dedicated warp) ====================
            TCGEN05_FENCE_AFTER();
            for (int i = 0; i < run_len; ++i) {
                const int tt = c + i;
                const int s  = tt & 3;
                MBARRIER_WAIT_PARITY(sb + SMEM_READY(s), (tt >> 2) & 1);
                if (elect_one()) {
                    issue_mma_ss(tmem + TMEM_D(s), sb + SMEM_A,
                                 sb + SMEM_B(s), sb + SMEM_FULL(s));
                }
            }
        } else {
            // ==================== consumer loop ====================
            const int ti = __ldg(&g_targ[rowbase + row]);
            float p = 0.0f, ng = 0.0f;

            for (int i = 0; i < run_len; ++i) {
                const int cc = c + i;
                const int s  = cc & 3;

                MBARRIER_WAIT_PARITY(sb + SMEM_READY(s), (cc >> 2) & 1); // tcol
                MBARRIER_WAIT_PARITY(sb + SMEM_FULL(s),  (cc >> 2) & 1); // D
                TCGEN05_FENCE_AFTER();

                const int colbase = (col0 + i) * TN;
                const bool do_pos = row_new && (colbase < n_new);
                const int* tc = (const int*)(smem + SMEM_TCOL(s)) + cblk;
                uint32_t dr[32];
                TCGEN05_LD_32X32B_X32(dr, tmem + TMEM_D(s) + cblk);
                TCGEN05_WAIT_LD();

                if (do_pos) {
                    #pragma unroll
                    for (int j = 0; j < 32; ++j) {
                        const float sv = __uint_as_float(dr[j]);
                        const int tj = tc[j];
                        if (ti != tj) { if (sv > MARGIN) ng += sv; }
                        else if (sv < 1.0f - EPSV) p += 1.0f - sv;
                    }
                } else {
                    #pragma unroll
                    for (int j = 0; j < 32; ++j) {
                        const float sv = __uint_as_float(dr[j]);
                        if (ti != tc[j] && sv > MARGIN) ng += sv;
                    }
                }
                TCGEN05_FENCE_BEFORE();
                MBARRIER_ARRIVE(sb + SMEM_EMPTY(s));   // slot consumed
            }

            atomicAdd(&g_neg[rowbase + row], ng);
            if (p != 0.0f) atomicAdd(&g_pos[rowbase + row], p);
        }

        c += run_len;
        t += run_len;
    }

    __syncthreads();
    if (wid == 0) TCGEN05_DEALLOC(tmem, TMEM_COLS);

    // ---- last CTA computes the final scalar ---------------------------------
    __threadfence();
    __shared__ int s_last;
    if (tid == 0)
        s_last = (atomicAdd(&g_done, 1) == gridDim.x - 1) ? 1 : 0;
    __syncthreads();
    if (s_last) {
        double* sh = reinterpret_cast<double*>(smem);
        const double a = (double)alpha;
        const double b = 1.0 - a;
        const double stale = (double)__ldcg(&g_pos[n_new - 1]);
        double s = 0.0;
        for (int i = tid; i < n; i += NTHREADS) {
            double pv = (i < n_new) ? (double)__ldcg(&g_pos[i]) : stale;
            s += a * pv + b * (double)__ldcg(&g_neg[i]);
        }
        sh[tid] = s;
        __syncthreads();
        for (int off = 256; off > 0; off >>= 1) {
            if (tid < off && tid + off < NTHREADS) sh[tid] += sh[tid + off];
            __syncthreads();
        }
        if (tid == 0) out[0] = (float)(sh[0] / (double)n);
    }
#endif  // HAS_TCGEN05
}

// ---------------------------------------------------------------------------
extern "C" void kernel_launch(void* const* d_in, const int* in_sizes, int n_in,
                              void* d_out, int out_size)
{
    const float* feat = (const float*)d_in[0];
    const void*  targ = d_in[1];

    const int n     = in_sizes[1];             // 8192
    const int d     = in_sizes[0] / n;         // 256
    const int n_new = in_sizes[2];             // 4096
    const int n_old = (n_in > 3) ? in_sizes[3] : 0;
    const float alpha = (n_old != 0) ? 0.9f : 0.5f;

    cudaFuncSetAttribute(sim_tc_kernel,
                         cudaFuncAttributeMaxDynamicSharedMemorySize, SMEM_TOTAL);

    {
        int total4 = (n * d) >> 2;
        convert_kernel<<<(total4 + 255) / 256, 256>>>(feat, targ, n, d);
    }
    sim_tc_kernel<<<GRID_CTAS, NTHREADS, SMEM_TOTAL>>>((float*)d_out, n, d, n_new, alpha);
}

// round 15
// speedup vs baseline: 1.1455x; 1.0434x over previous
#include <cuda_runtime.h>
#include <cuda_bf16.h>
#include <cstdint>

#define MARGIN 0.5f
#define EPSV   1e-5f

#define N_MAX  8192
#define D_MAX  256
#define TM 256                      // double-slab: 2 x 128 rows per window
#define TN 64

#if defined(__CUDA_ARCH__) && (__CUDA_ARCH__ == 1030) && defined(__CUDA_ARCH_FEAT_SM103_ALL)
#define HAS_TCGEN05 1
#else
#define HAS_TCGEN05 0
#endif

// ---------------------------------------------------------------------------
// Device scratch
// ---------------------------------------------------------------------------
__device__ float          g_pos[N_MAX];
__device__ float          g_neg[N_MAX];
__device__ int            g_targ[N_MAX];
__device__ __nv_bfloat16  g_featbf[N_MAX * D_MAX];
__device__ int            g_done;

// ---------------------------------------------------------------------------
// Prep: fp32->bf16 features, target->int32 (inline int64/int32 probe),
// zero accumulators + ticket.
// ---------------------------------------------------------------------------
__global__ void convert_kernel(const float* __restrict__ feat,
                               const void* __restrict__ targ, int n, int d) {
    __shared__ int s_is64;
    const int i = blockIdx.x * blockDim.x + threadIdx.x;

    const bool need_t = (blockIdx.x * blockDim.x) < n;
    if (need_t) {
        if (threadIdx.x == 0) {
            const long long* t = (const long long*)targ;
            int m = n / 2; if (m > 33) m = 33;
            bool is64 = true;
            for (int k = 1; k < m; ++k) {
                long long v = t[k];
                if (v < 0 || v >= (1LL << 30)) { is64 = false; break; }
            }
            s_is64 = is64 ? 1 : 0;
        }
        __syncthreads();
    }

    const int total4 = (n * d) >> 2;
    if (i < total4) {
        float4 v = reinterpret_cast<const float4*>(feat)[i];
        __nv_bfloat162 lo = __nv_bfloat162(__float2bfloat16(v.x), __float2bfloat16(v.y));
        __nv_bfloat162 hi = __nv_bfloat162(__float2bfloat16(v.z), __float2bfloat16(v.w));
        reinterpret_cast<__nv_bfloat162*>(g_featbf)[i * 2 + 0] = lo;
        reinterpret_cast<__nv_bfloat162*>(g_featbf)[i * 2 + 1] = hi;
    }
    if (i < n) {
        g_pos[i] = 0.0f; g_neg[i] = 0.0f;
        g_targ[i] = s_is64 ? (int)((const long long*)targ)[i]
                           : ((const int*)targ)[i];
    }
    if (i == 0) g_done = 0;
}

// ---------------------------------------------------------------------------
// PTX helpers
// ---------------------------------------------------------------------------
__device__ __forceinline__ uint32_t smem_u32(const void* p) {
    uint32_t a;
    asm("{ .reg .u64 t; cvta.to.shared.u64 t, %1; cvt.u32.u64 %0, t; }"
        : "=r"(a) : "l"(p));
    return a;
}

__device__ __forceinline__ uint32_t elect_one() {
    uint32_t pred;
    asm volatile("{\n\t.reg .pred p;\n\telect.sync _|p, 0xFFFFFFFF;\n\t"
                 "selp.b32 %0, 1, 0, p;\n\t}" : "=r"(pred));
    return pred;
}

#define MBARRIER_INIT(mbar, count) \
    asm volatile("mbarrier.init.shared.b64 [%0], %1;" \
                 :: "r"((uint32_t)(mbar)), "r"((uint32_t)(count)) : "memory")

#define MBARRIER_ARRIVE(mbar) \
    asm volatile("mbarrier.arrive.shared.b64 _, [%0];" \
                 :: "r"((uint32_t)(mbar)) : "memory")

#define MBARRIER_WAIT_PARITY(mbar, parity) do {                                   \
    uint32_t _m = (uint32_t)(mbar); uint32_t _p = (uint32_t)(parity);             \
    uint32_t _done;                                                               \
    asm volatile("{\n\t.reg .pred p;\n\t"                                         \
        "mbarrier.try_wait.parity.acquire.cta.shared::cta.b64 p, [%1], %2;\n\t"   \
        "selp.b32 %0, 1, 0, p;\n\t}" : "=r"(_done) : "r"(_m), "r"(_p) : "memory");\
    if (!_done) {                                                                 \
        asm volatile("{\n\t.reg .pred P1;\n\t"                                    \
            "WAIT_LOOP_%=:\n\t"                                                   \
            "mbarrier.try_wait.parity.acquire.cta.shared::cta.b64 P1, [%0], %1, 0x989680;\n\t" \
            "@P1 bra.uni WAIT_DONE_%=;\n\t"                                       \
            "bra.uni WAIT_LOOP_%=;\n\t"                                           \
            "WAIT_DONE_%=:\n\t}" :: "r"(_m), "r"(_p) : "memory");                 \
    }                                                                             \
} while (0)

#if HAS_TCGEN05

#define TCGEN05_ALLOC(sm_addr, nCols) \
    asm volatile("tcgen05.alloc.cta_group::1.sync.aligned.shared::cta.b32 [%0], %1;" \
                 :: "r"((uint32_t)(sm_addr)), "r"((uint32_t)(nCols)) : "memory")
#define TCGEN05_DEALLOC(tmem_addr, nCols) \
    asm volatile("tcgen05.dealloc.cta_group::1.sync.aligned.b32 %0, %1;" \
                 :: "r"(tmem_addr), "r"((uint32_t)(nCols)))
#define TCGEN05_RELINQUISH() \
    asm volatile("tcgen05.relinquish_alloc_permit.cta_group::1.sync.aligned;")
#define TCGEN05_COMMIT(mbar) \
    asm volatile("tcgen05.commit.cta_group::1.mbarrier::arrive::one.shared::cluster.b64 [%0];" \
                 :: "r"((uint32_t)(mbar)) : "memory")
#define TCGEN05_FENCE_AFTER()  asm volatile("tcgen05.fence::after_thread_sync;"  ::: "memory")
#define TCGEN05_FENCE_BEFORE() asm volatile("tcgen05.fence::before_thread_sync;" ::: "memory")
#define TCGEN05_WAIT_LD()      asm volatile("tcgen05.wait::ld.sync.aligned;"     ::: "memory")

#define TCGEN05_LD_32X32B_X32(r, tmem_addr) \
    asm volatile( \
        "tcgen05.ld.sync.aligned.32x32b.x32.b32 " \
        "{%0, %1, %2, %3, %4, %5, %6, %7, " \
        " %8, %9, %10, %11, %12, %13, %14, %15, " \
        " %16, %17, %18, %19, %20, %21, %22, %23, " \
        " %24, %25, %26, %27, %28, %29, %30, %31}, [%32];" \
        : "=r"((r)[0]),  "=r"((r)[1]),  "=r"((r)[2]),  "=r"((r)[3]), \
          "=r"((r)[4]),  "=r"((r)[5]),  "=r"((r)[6]),  "=r"((r)[7]), \
          "=r"((r)[8]),  "=r"((r)[9]),  "=r"((r)[10]), "=r"((r)[11]), \
          "=r"((r)[12]), "=r"((r)[13]), "=r"((r)[14]), "=r"((r)[15]), \
          "=r"((r)[16]), "=r"((r)[17]), "=r"((r)[18]), "=r"((r)[19]), \
          "=r"((r)[20]), "=r"((r)[21]), "=r"((r)[22]), "=r"((r)[23]), \
          "=r"((r)[24]), "=r"((r)[25]), "=r"((r)[26]), "=r"((r)[27]), \
          "=r"((r)[28]), "=r"((r)[29]), "=r"((r)[30]), "=r"((r)[31]) \
        : "r"(tmem_addr))

// SW128 K-major descriptor: version=1, SBO=64, LBO=1
static constexpr uint64_t SMEM_DESC_BASE_SW128 =
    (uint64_t(2)  << 61) | (uint64_t(1) << 46) | (uint64_t(64) << 32) | (uint64_t(1) << 16);

__device__ __forceinline__ uint64_t make_desc(uint32_t addr) {
    return SMEM_DESC_BASE_SW128 | ((uint64_t)(addr >> 4) & 0x3FFF);
}

// SS-mode bf16 MMA: A in SMEM, B in SMEM
__device__ __forceinline__ void mma_f16_ss(uint32_t d_tmem, uint64_t a_desc,
                                           uint64_t b_desc, uint32_t idesc, bool acc) {
    uint32_t en = acc ? 1u : 0u;
    asm volatile(
        "{\n\t.reg .pred p;\n\tsetp.ne.u32 p, %5, 0;\n\t"
        "tcgen05.mma.cta_group::1.kind::f16 [%0], %1, %2, %3, {%4, %4, %4, %4}, p;\n\t}"
        :: "r"(d_tmem), "l"(a_desc), "l"(b_desc), "r"(idesc), "r"(0u), "r"(en)
        : "memory");
}

// fp32 acc, bf16 a/b, M=128 (per chain), N=64
static constexpr uint32_t MMA_IDESC =
    (1u << 4) | (1u << 7) | (1u << 10) | ((TN / 8) << 17) | (8u << 24);

#endif  // HAS_TCGEN05

// ---------------------------------------------------------------------------
// SMEM layout (per CTA): A0+A1 (128 KB) + 2 B buffers + 2 tcol + mbars
// ---------------------------------------------------------------------------
#define SMEM_A(h)     ((h) * 65536)            // 2 x 64 KB (128 rows x 256 bf16)
#define SMEM_B(b)     (131072 + (b) * 32768)   // 2 x 32 KB
#define SMEM_TCOL(b)  (196608 + (b) * 256)     // 2 x 256 B
#define SMEM_FULL(s)  (197120 + (s) * 8)       // 2 (MMA commit, count 1)
#define SMEM_EMPTY(s) (197136 + (s) * 8)       // 2 (epilogue done, count 256)
#define SMEM_READY(s) (197152 + (s) * 8)       // 2 (B+tcol loaded, count 128)
#define SMEM_TMEMPTR  197168
#define SMEM_TOTAL    197200

#define TMEM_COLS     256          // 2 slots x (64 D0 + 64 D1)
#define TMEM_D(s)     ((s) * 128)

#define GRID_CTAS     148
#define NTHREADS      416          // 8 epilogue + 4 loader + 1 issuer warps

#if HAS_TCGEN05
// Load one 64-row x 256-col bf16 B tile into SW128 K-major blocked-atom
// layout (8 atom-rows; atom-col stride 8 KB). 128 threads.
__device__ __forceinline__ void load_tileB(char* smem, uint32_t dst,
                                           int gbase, int lt) {
    const uint4* src = reinterpret_cast<const uint4*>(g_featbf);
    #pragma unroll
    for (int k = 0; k < 16; ++k) {
        int idx = lt + k * 128;              // 0..2047
        int r = idx >> 5, ch = idx & 31;
        uint32_t byte = ((uint32_t)((r >> 3) + (ch >> 3) * 8) << 10)
                      + ((uint32_t)(r & 7) << 7) + ((uint32_t)(ch & 7) << 4);
        uint32_t sw = byte ^ ((byte >> 3) & 0x70);
        *reinterpret_cast<uint4*>(smem + dst + sw) =
            src[(size_t)(gbase + r) * 32 + ch];
    }
}

// Load one 128-row x 256-col A half into SW128 K-major blocked-atom layout
// (16 atom-rows; atom-col stride 16 KB). NT cooperating threads.
__device__ __forceinline__ void load_tileA(char* smem, uint32_t dst,
                                           int gbase, int tid, int nt) {
    const uint4* src = reinterpret_cast<const uint4*>(g_featbf);
    for (int idx = tid; idx < 4096; idx += nt) {
        int r = idx >> 5, ch = idx & 31;
        uint32_t byte = ((uint32_t)((r >> 3) + (ch >> 3) * 16) << 10)
                      + ((uint32_t)(r & 7) << 7) + ((uint32_t)(ch & 7) << 4);
        uint32_t sw = byte ^ ((byte >> 3) & 0x70);
        *reinterpret_cast<uint4*>(smem + dst + sw) =
            src[(size_t)(gbase + r) * 32 + ch];
    }
}

// Double-M SS MMA batch: A0 x B -> D0 (64 cols), A1 x B -> D1 (next 64),
// 16 chained K=16 steps each, single commit at the end.
// A desc: atom-col stride 16 KB = 1024 units; B: 8 KB = 512 units; +2/step.
__device__ __forceinline__ void issue_mma_ss2(uint32_t d_tmem,
                                              uint32_t a0_addr, uint32_t a1_addr,
                                              uint32_t b_addr, uint32_t mbar) {
    uint64_t a0 = make_desc(a0_addr);
    uint64_t a1 = make_desc(a1_addr);
    uint64_t bb = make_desc(b_addr);
    #pragma unroll
    for (int s = 0; s < 16; ++s) {
        uint64_t aoff = ((uint64_t)(s >> 2) << 10) | (uint64_t)((s & 3) << 1);
        uint64_t boff = ((uint64_t)(s >> 2) << 9)  | (uint64_t)((s & 3) << 1);
        mma_f16_ss(d_tmem, a0 + aoff, bb + boff, MMA_IDESC, s > 0);
    }
    #pragma unroll
    for (int s = 0; s < 16; ++s) {
        uint64_t aoff = ((uint64_t)(s >> 2) << 10) | (uint64_t)((s & 3) << 1);
        uint64_t boff = ((uint64_t)(s >> 2) << 9)  | (uint64_t)((s & 3) << 1);
        mma_f16_ss(d_tmem + 64, a1 + aoff, bb + boff, MMA_IDESC, s > 0);
    }
    TCGEN05_COMMIT(mbar);
}
#endif

// ---------------------------------------------------------------------------
// Persistent depth-2 pipeline, 256-row double-slab windows, dedicated issuer.
//   warps 0-7  (consumers): warp w -> A-half (w>>2), rows (w&3)*32+lane,
//                           all 64 cols (2x LDTM x32); arrive EMPTY.
//   warps 8-11 (producers): load B(tt)+tcol(tt) after EMPTY(tt-2); arrive READY.
//   warp  12   (issuer):    wait READY(tt), issue 2x16 SS MMAs, commit FULL(tt).
// Slots = tt & 1; phase parity = (tt >> 1) & 1 (global tile counter).
// Halves both window count and B L2 traffic vs the 128-row version.
// ---------------------------------------------------------------------------
__global__ __launch_bounds__(NTHREADS, 1)
void sim_tc_kernel(float* out, int n, int d, int n_new, float alpha)
{
#if HAS_TCGEN05
    extern __shared__ __align__(1024) char smem[];
    const uint32_t sb = smem_u32(smem);
    const int tid  = threadIdx.x;
    const int wid  = tid >> 5;
    const int lane = tid & 31;

    if (wid == 0) {
        TCGEN05_ALLOC(sb + SMEM_TMEMPTR, TMEM_COLS);
        TCGEN05_RELINQUISH();
    }
    if (tid == 0) {
        #pragma unroll
        for (int s = 0; s < 2; ++s) {
            MBARRIER_INIT(sb + SMEM_FULL(s), 1);
            MBARRIER_INIT(sb + SMEM_EMPTY(s), 256);
            MBARRIER_INIT(sb + SMEM_READY(s), 128);
        }
    }
    __syncthreads();

    uint32_t tmem;
    asm volatile("ld.shared.b32 %0, [%1];" : "=r"(tmem) : "r"(sb + SMEM_TMEMPTR));

    // ---- tile enumeration (256-row double slabs, TN=64 columns) --------------
    const int slabs_new = n_new / TM;            // 16
    const int cols_full = n / TN;                // 128
    const int cols_new  = n_new / TN;            // 64
    const int slabs_tot = n / TM;                // 32
    const int tiles_new = slabs_new * cols_full; // 2048
    const int tiles_tot = tiles_new + (slabs_tot - slabs_new) * cols_new; // 3072

    const int G = gridDim.x;
    int t   = (int)((long long)blockIdx.x       * tiles_tot / G);
    int end = (int)((long long)(blockIdx.x + 1) * tiles_tot / G);

    const int role = (wid < 8) ? 0 : (wid < 12 ? 1 : 2);   // 0=cons,1=prod,2=issuer
    const int lt   = tid - 256;                  // producer-local tid (0..127)
    const int half = wid >> 2;                   // consumer A-half (0/1), wid<8
    const int srow = (wid & 3) * 32 + lane;      // consumer row within half

    int c = 0;                                   // global tile counter

    while (t < end) {
        // decode run: contiguous tiles sharing one double slab
        int slab, col0, slab_cols, slab_t0;
        if (t < tiles_new) {
            slab = t / cols_full; col0 = t - slab * cols_full;
            slab_cols = cols_full; slab_t0 = slab * cols_full;
        } else {
            int u = t - tiles_new;
            slab = slabs_new + u / cols_new; col0 = u % cols_new;
            slab_cols = cols_new;
            slab_t0 = tiles_new + (slab - slabs_new) * cols_new;
        }
        int run_len = slab_t0 + slab_cols - t;
        if (run_len > end - t) run_len = end - t;
        const int rowbase = slab * TM;
        const bool row_new = slab < slabs_new;   // uniform per double slab

        // ---- run boundary: drain, load both A halves into SMEM ---------------
        __syncthreads();
        load_tileA(smem, SMEM_A(0), rowbase,       tid, NTHREADS);
        load_tileA(smem, SMEM_A(1), rowbase + 128, tid, NTHREADS);
        asm volatile("fence.proxy.async.shared::cta;" ::: "memory");
        __syncthreads();                         // A visible before any MMA

        if (role == 1) {
            // ==================== producer loop ====================
            for (int i = 0; i < run_len; ++i) {
                const int tt = c + i;
                const int s  = tt & 1;
                const int colbase = (col0 + i) * TN;

                // slot free: consumer(tt-2) done
                if (tt >= 2)
                    MBARRIER_WAIT_PARITY(sb + SMEM_EMPTY(s),
                                         ((tt >> 1) & 1) ^ 1);

                load_tileB(smem, SMEM_B(s), colbase, lt);
                if (lt < TN)
                    ((int*)(smem + SMEM_TCOL(s)))[lt] = g_targ[colbase + lt];
                asm volatile("fence.proxy.async.shared::cta;" ::: "memory");
                MBARRIER_ARRIVE(sb + SMEM_READY(s));
            }
        } else if (role == 2) {
            // ==================== issuer loop (dedicated warp) ====================
            TCGEN05_FENCE_AFTER();
            for (int i = 0; i < run_len; ++i) {
                const int tt = c + i;
                const int s  = tt & 1;
                MBARRIER_WAIT_PARITY(sb + SMEM_READY(s), (tt >> 1) & 1);
                if (elect_one()) {
                    issue_mma_ss2(tmem + TMEM_D(s), sb + SMEM_A(0), sb + SMEM_A(1),
                                  sb + SMEM_B(s), sb + SMEM_FULL(s));
                }
            }
        } else {
            // ==================== consumer loop ====================
            const int grow = rowbase + half * 128 + srow;
            const int ti = __ldg(&g_targ[grow]);
            float p = 0.0f, ng = 0.0f;

            for (int i = 0; i < run_len; ++i) {
                const int cc = c + i;
                const int s  = cc & 1;

                MBARRIER_WAIT_PARITY(sb + SMEM_READY(s), (cc >> 1) & 1); // tcol
                MBARRIER_WAIT_PARITY(sb + SMEM_FULL(s),  (cc >> 1) & 1); // D
                TCGEN05_FENCE_AFTER();

                const int colbase = (col0 + i) * TN;
                const bool do_pos = row_new && (colbase < n_new);
                const int* tc = (const int*)(smem + SMEM_TCOL(s));
                const uint32_t dbase = tmem + TMEM_D(s) + half * 64;
                uint32_t dr[32];

                #pragma unroll
                for (int q = 0; q < 2; ++q) {
                    TCGEN05_LD_32X32B_X32(dr, dbase + q * 32);
                    TCGEN05_WAIT_LD();
                    if (do_pos) {
                        #pragma unroll
                        for (int j = 0; j < 32; ++j) {
                            const float sv = __uint_as_float(dr[j]);
                            const int tj = tc[q * 32 + j];
                            if (ti != tj) { if (sv > MARGIN) ng += sv; }
                            else if (sv < 1.0f - EPSV) p += 1.0f - sv;
                        }
                    } else {
                        #pragma unroll
                        for (int j = 0; j < 32; ++j) {
                            const float sv = __uint_as_float(dr[j]);
                            if (ti != tc[q * 32 + j] && sv > MARGIN) ng += sv;
                        }
                    }
                }
                TCGEN05_FENCE_BEFORE();
                MBARRIER_ARRIVE(sb + SMEM_EMPTY(s));   // slot consumed
            }

            atomicAdd(&g_neg[grow], ng);
            if (p != 0.0f) atomicAdd(&g_pos[grow], p);
        }

        c += run_len;
        t += run_len;
    }

    __syncthreads();
    if (wid == 0) TCGEN05_DEALLOC(tmem, TMEM_COLS);

    // ---- last CTA computes the final scalar ---------------------------------
    __threadfence();
    __shared__ int s_last;
    if (tid == 0)
        s_last = (atomicAdd(&g_done, 1) == gridDim.x - 1) ? 1 : 0;
    __syncthreads();
    if (s_last) {
        double* sh = reinterpret_cast<double*>(smem);
        const double a = (double)alpha;
        const double b = 1.0 - a;
        const double stale = (double)__ldcg(&g_pos[n_new - 1]);
        double s = 0.0;
        for (int i = tid; i < n; i += NTHREADS) {
            double pv = (i < n_new) ? (double)__ldcg(&g_pos[i]) : stale;
            s += a * pv + b * (double)__ldcg(&g_neg[i]);
        }
        sh[tid] = s;
        __syncthreads();
        for (int off = 256; off > 0; off >>= 1) {
            if (tid < off && tid + off < NTHREADS) sh[tid] += sh[tid + off];
            __syncthreads();
        }
        if (tid == 0) out[0] = (float)(sh[0] / (double)n);
    }
#endif  // HAS_TCGEN05
}

// ---------------------------------------------------------------------------
extern "C" void kernel_launch(void* const* d_in, const int* in_sizes, int n_in,
                              void* d_out, int out_size)
{
    const float* feat = (const float*)d_in[0];
    const void*  targ = d_in[1];

    const int n     = in_sizes[1];             // 8192
    const int d     = in_sizes[0] / n;         // 256
    const int n_new = in_sizes[2];             // 4096
    const int n_old = (n_in > 3) ? in_sizes[3] : 0;
    const float alpha = (n_old != 0) ? 0.9f : 0.5f;

    cudaFuncSetAttribute(sim_tc_kernel,
                         cudaFuncAttributeMaxDynamicSharedMemorySize, SMEM_TOTAL);

    {
        int total4 = (n * d) >> 2;
        convert_kernel<<<(total4 + 255) / 256, 256>>>(feat, targ, n, d);
    }
    sim_tc_kernel<<<GRID_CTAS, NTHREADS, SMEM_TOTAL>>>((float*)d_out, n, d, n_new, alpha);
}

// round 16
// speedup vs baseline: 1.2366x; 1.0795x over previous
#include <cuda_runtime.h>
#include <cuda_bf16.h>
#include <cstdint>

#define MARGIN 0.5f
#define EPSV   1e-5f

#define N_MAX  8192
#define D_MAX  256
#define TM 256                      // double-slab: 2 x 128 rows per window
#define TN 64

#if defined(__CUDA_ARCH__) && (__CUDA_ARCH__ == 1030) && defined(__CUDA_ARCH_FEAT_SM103_ALL)
#define HAS_TCGEN05 1
#else
#define HAS_TCGEN05 0
#endif

// ---------------------------------------------------------------------------
// Device scratch
// ---------------------------------------------------------------------------
__device__ float          g_pos[N_MAX];
__device__ float          g_neg[N_MAX];
__device__ int            g_targ[N_MAX];
__device__ __nv_bfloat16  g_featbf[N_MAX * D_MAX];
__device__ int            g_done;

// ---------------------------------------------------------------------------
// Prep: fp32->bf16 features, target->int32 (inline int64/int32 probe),
// zero accumulators + ticket.
// ---------------------------------------------------------------------------
__global__ void convert_kernel(const float* __restrict__ feat,
                               const void* __restrict__ targ, int n, int d) {
    __shared__ int s_is64;
    const int i = blockIdx.x * blockDim.x + threadIdx.x;

    const bool need_t = (blockIdx.x * blockDim.x) < n;
    if (need_t) {
        if (threadIdx.x == 0) {
            const long long* t = (const long long*)targ;
            int m = n / 2; if (m > 33) m = 33;
            bool is64 = true;
            for (int k = 1; k < m; ++k) {
                long long v = t[k];
                if (v < 0 || v >= (1LL << 30)) { is64 = false; break; }
            }
            s_is64 = is64 ? 1 : 0;
        }
        __syncthreads();
    }

    const int total4 = (n * d) >> 2;
    if (i < total4) {
        float4 v = reinterpret_cast<const float4*>(feat)[i];
        __nv_bfloat162 lo = __nv_bfloat162(__float2bfloat16(v.x), __float2bfloat16(v.y));
        __nv_bfloat162 hi = __nv_bfloat162(__float2bfloat16(v.z), __float2bfloat16(v.w));
        reinterpret_cast<__nv_bfloat162*>(g_featbf)[i * 2 + 0] = lo;
        reinterpret_cast<__nv_bfloat162*>(g_featbf)[i * 2 + 1] = hi;
    }
    if (i < n) {
        g_pos[i] = 0.0f; g_neg[i] = 0.0f;
        g_targ[i] = s_is64 ? (int)((const long long*)targ)[i]
                           : ((const int*)targ)[i];
    }
    if (i == 0) g_done = 0;
}

// ---------------------------------------------------------------------------
// PTX helpers
// ---------------------------------------------------------------------------
__device__ __forceinline__ uint32_t smem_u32(const void* p) {
    uint32_t a;
    asm("{ .reg .u64 t; cvta.to.shared.u64 t, %1; cvt.u32.u64 %0, t; }"
        : "=r"(a) : "l"(p));
    return a;
}

__device__ __forceinline__ uint32_t elect_one() {
    uint32_t pred;
    asm volatile("{\n\t.reg .pred p;\n\telect.sync _|p, 0xFFFFFFFF;\n\t"
                 "selp.b32 %0, 1, 0, p;\n\t}" : "=r"(pred));
    return pred;
}

#define MBARRIER_INIT(mbar, count) \
    asm volatile("mbarrier.init.shared.b64 [%0], %1;" \
                 :: "r"((uint32_t)(mbar)), "r"((uint32_t)(count)) : "memory")

#define MBARRIER_ARRIVE(mbar) \
    asm volatile("mbarrier.arrive.shared.b64 _, [%0];" \
                 :: "r"((uint32_t)(mbar)) : "memory")

#define MBARRIER_WAIT_PARITY(mbar, parity) do {                                   \
    uint32_t _m = (uint32_t)(mbar); uint32_t _p = (uint32_t)(parity);             \
    uint32_t _done;                                                               \
    asm volatile("{\n\t.reg .pred p;\n\t"                                         \
        "mbarrier.try_wait.parity.acquire.cta.shared::cta.b64 p, [%1], %2;\n\t"   \
        "selp.b32 %0, 1, 0, p;\n\t}" : "=r"(_done) : "r"(_m), "r"(_p) : "memory");\
    if (!_done) {                                                                 \
        asm volatile("{\n\t.reg .pred P1;\n\t"                                    \
            "WAIT_LOOP_%=:\n\t"                                                   \
            "mbarrier.try_wait.parity.acquire.cta.shared::cta.b64 P1, [%0], %1, 0x989680;\n\t" \
            "@P1 bra.uni WAIT_DONE_%=;\n\t"                                       \
            "bra.uni WAIT_LOOP_%=;\n\t"                                           \
            "WAIT_DONE_%=:\n\t}" :: "r"(_m), "r"(_p) : "memory");                 \
    }                                                                             \
} while (0)

#if HAS_TCGEN05

#define TCGEN05_ALLOC(sm_addr, nCols) \
    asm volatile("tcgen05.alloc.cta_group::1.sync.aligned.shared::cta.b32 [%0], %1;" \
                 :: "r"((uint32_t)(sm_addr)), "r"((uint32_t)(nCols)) : "memory")
#define TCGEN05_DEALLOC(tmem_addr, nCols) \
    asm volatile("tcgen05.dealloc.cta_group::1.sync.aligned.b32 %0, %1;" \
                 :: "r"(tmem_addr), "r"((uint32_t)(nCols)))
#define TCGEN05_RELINQUISH() \
    asm volatile("tcgen05.relinquish_alloc_permit.cta_group::1.sync.aligned;")
#define TCGEN05_COMMIT(mbar) \
    asm volatile("tcgen05.commit.cta_group::1.mbarrier::arrive::one.shared::cluster.b64 [%0];" \
                 :: "r"((uint32_t)(mbar)) : "memory")
#define TCGEN05_FENCE_AFTER()  asm volatile("tcgen05.fence::after_thread_sync;"  ::: "memory")
#define TCGEN05_FENCE_BEFORE() asm volatile("tcgen05.fence::before_thread_sync;" ::: "memory")
#define TCGEN05_WAIT_LD()      asm volatile("tcgen05.wait::ld.sync.aligned;"     ::: "memory")

#define TCGEN05_LD_32X32B_X32(r, tmem_addr) \
    asm volatile( \
        "tcgen05.ld.sync.aligned.32x32b.x32.b32 " \
        "{%0, %1, %2, %3, %4, %5, %6, %7, " \
        " %8, %9, %10, %11, %12, %13, %14, %15, " \
        " %16, %17, %18, %19, %20, %21, %22, %23, " \
        " %24, %25, %26, %27, %28, %29, %30, %31}, [%32];" \
        : "=r"((r)[0]),  "=r"((r)[1]),  "=r"((r)[2]),  "=r"((r)[3]), \
          "=r"((r)[4]),  "=r"((r)[5]),  "=r"((r)[6]),  "=r"((r)[7]), \
          "=r"((r)[8]),  "=r"((r)[9]),  "=r"((r)[10]), "=r"((r)[11]), \
          "=r"((r)[12]), "=r"((r)[13]), "=r"((r)[14]), "=r"((r)[15]), \
          "=r"((r)[16]), "=r"((r)[17]), "=r"((r)[18]), "=r"((r)[19]), \
          "=r"((r)[20]), "=r"((r)[21]), "=r"((r)[22]), "=r"((r)[23]), \
          "=r"((r)[24]), "=r"((r)[25]), "=r"((r)[26]), "=r"((r)[27]), \
          "=r"((r)[28]), "=r"((r)[29]), "=r"((r)[30]), "=r"((r)[31]) \
        : "r"(tmem_addr))

// SW128 K-major descriptor: version=1, SBO=64, LBO=1
static constexpr uint64_t SMEM_DESC_BASE_SW128 =
    (uint64_t(2)  << 61) | (uint64_t(1) << 46) | (uint64_t(64) << 32) | (uint64_t(1) << 16);

__device__ __forceinline__ uint64_t make_desc(uint32_t addr) {
    return SMEM_DESC_BASE_SW128 | ((uint64_t)(addr >> 4) & 0x3FFF);
}

// SS-mode bf16 MMA: A in SMEM, B in SMEM
__device__ __forceinline__ void mma_f16_ss(uint32_t d_tmem, uint64_t a_desc,
                                           uint64_t b_desc, uint32_t idesc, bool acc) {
    uint32_t en = acc ? 1u : 0u;
    asm volatile(
        "{\n\t.reg .pred p;\n\tsetp.ne.u32 p, %5, 0;\n\t"
        "tcgen05.mma.cta_group::1.kind::f16 [%0], %1, %2, %3, {%4, %4, %4, %4}, p;\n\t}"
        :: "r"(d_tmem), "l"(a_desc), "l"(b_desc), "r"(idesc), "r"(0u), "r"(en)
        : "memory");
}

// fp32 acc, bf16 a/b, M=128 (per chain), N=64
static constexpr uint32_t MMA_IDESC =
    (1u << 4) | (1u << 7) | (1u << 10) | ((TN / 8) << 17) | (8u << 24);

#endif  // HAS_TCGEN05

// ---------------------------------------------------------------------------
// SMEM layout (per CTA): A0+A1 (128 KB) + 2 B buffers + 4 tcol + mbars
// ---------------------------------------------------------------------------
#define SMEM_A(h)     ((h) * 65536)            // 2 x 64 KB
#define SMEM_B(b)     (131072 + (b) * 32768)   // 2 x 32 KB
#define SMEM_TCOL(b)  (196608 + (b) * 256)     // 4 x 256 B (depth 4!)
#define SMEM_FULL(s)  (197632 + (s) * 8)       // 2 (MMA commit, count 1)
#define SMEM_EMPTY(s) (197648 + (s) * 8)       // 2 (D consumed, count 256)
#define SMEM_READY(s) (197664 + (s) * 8)       // 4 (B+tcol loaded, count 128)
#define SMEM_TMEMPTR  197696
#define SMEM_TOTAL    197728

#define TMEM_COLS     256          // 2 slots x (64 D0 + 64 D1)
#define TMEM_D(s)     ((s) * 128)

#define GRID_CTAS     148
#define NTHREADS      416          // 8 epilogue + 4 loader + 1 issuer warps

#if HAS_TCGEN05
// Load one 64-row x 256-col bf16 B tile into SW128 K-major blocked-atom
// layout (8 atom-rows; atom-col stride 8 KB). 128 threads.
__device__ __forceinline__ void load_tileB(char* smem, uint32_t dst,
                                           int gbase, int lt) {
    const uint4* src = reinterpret_cast<const uint4*>(g_featbf);
    #pragma unroll
    for (int k = 0; k < 16; ++k) {
        int idx = lt + k * 128;              // 0..2047
        int r = idx >> 5, ch = idx & 31;
        uint32_t byte = ((uint32_t)((r >> 3) + (ch >> 3) * 8) << 10)
                      + ((uint32_t)(r & 7) << 7) + ((uint32_t)(ch & 7) << 4);
        uint32_t sw = byte ^ ((byte >> 3) & 0x70);
        *reinterpret_cast<uint4*>(smem + dst + sw) =
            src[(size_t)(gbase + r) * 32 + ch];
    }
}

// Load one 128-row x 256-col A half into SW128 K-major blocked-atom layout
// (16 atom-rows; atom-col stride 16 KB). NT cooperating threads.
__device__ __forceinline__ void load_tileA(char* smem, uint32_t dst,
                                           int gbase, int tid, int nt) {
    const uint4* src = reinterpret_cast<const uint4*>(g_featbf);
    for (int idx = tid; idx < 4096; idx += nt) {
        int r = idx >> 5, ch = idx & 31;
        uint32_t byte = ((uint32_t)((r >> 3) + (ch >> 3) * 16) << 10)
                      + ((uint32_t)(r & 7) << 7) + ((uint32_t)(ch & 7) << 4);
        uint32_t sw = byte ^ ((byte >> 3) & 0x70);
        *reinterpret_cast<uint4*>(smem + dst + sw) =
            src[(size_t)(gbase + r) * 32 + ch];
    }
}

// Double-M SS MMA batch: A0 x B -> D0 (64 cols), A1 x B -> D1 (next 64),
// 16 chained K=16 steps each, single commit.
__device__ __forceinline__ void issue_mma_ss2(uint32_t d_tmem,
                                              uint32_t a0_addr, uint32_t a1_addr,
                                              uint32_t b_addr, uint32_t mbar) {
    uint64_t a0 = make_desc(a0_addr);
    uint64_t a1 = make_desc(a1_addr);
    uint64_t bb = make_desc(b_addr);
    #pragma unroll
    for (int s = 0; s < 16; ++s) {
        uint64_t aoff = ((uint64_t)(s >> 2) << 10) | (uint64_t)((s & 3) << 1);
        uint64_t boff = ((uint64_t)(s >> 2) << 9)  | (uint64_t)((s & 3) << 1);
        mma_f16_ss(d_tmem, a0 + aoff, bb + boff, MMA_IDESC, s > 0);
    }
    #pragma unroll
    for (int s = 0; s < 16; ++s) {
        uint64_t aoff = ((uint64_t)(s >> 2) << 10) | (uint64_t)((s & 3) << 1);
        uint64_t boff = ((uint64_t)(s >> 2) << 9)  | (uint64_t)((s & 3) << 1);
        mma_f16_ss(d_tmem + 64, a1 + aoff, bb + boff, MMA_IDESC, s > 0);
    }
    TCGEN05_COMMIT(mbar);
}
#endif

// ---------------------------------------------------------------------------
// Persistent depth-2 pipeline, 256-row windows, dedicated issuer, SHORT RING:
//   consumers issue BOTH LDTMs back-to-back, wait once, then arrive EMPTY
//   IMMEDIATELY (D in regs; tcol protected by 4-deep buffering) so mask
//   processing overlaps producer(t+2) and MMA(t+1).
//   warps 0-7  (consumers): A-half (w>>2), rows (w&3)*32+lane, 64 cols.
//   warps 8-11 (producers): B(tt&1)+tcol(tt&3) after EMPTY(tt-2); arrive READY.
//   warp  12   (issuer):    wait READY(tt&3), issue 2x16 SS MMAs, commit FULL.
// ---------------------------------------------------------------------------
__global__ __launch_bounds__(NTHREADS, 1)
void sim_tc_kernel(float* out, int n, int d, int n_new, float alpha)
{
#if HAS_TCGEN05
    extern __shared__ __align__(1024) char smem[];
    const uint32_t sb = smem_u32(smem);
    const int tid  = threadIdx.x;
    const int wid  = tid >> 5;
    const int lane = tid & 31;

    if (wid == 0) {
        TCGEN05_ALLOC(sb + SMEM_TMEMPTR, TMEM_COLS);
        TCGEN05_RELINQUISH();
    }
    if (tid == 0) {
        #pragma unroll
        for (int s = 0; s < 2; ++s) {
            MBARRIER_INIT(sb + SMEM_FULL(s), 1);
            MBARRIER_INIT(sb + SMEM_EMPTY(s), 256);
        }
        #pragma unroll
        for (int s = 0; s < 4; ++s)
            MBARRIER_INIT(sb + SMEM_READY(s), 128);
    }
    __syncthreads();

    uint32_t tmem;
    asm volatile("ld.shared.b32 %0, [%1];" : "=r"(tmem) : "r"(sb + SMEM_TMEMPTR));

    // ---- tile enumeration (256-row double slabs, TN=64 columns) --------------
    const int slabs_new = n_new / TM;            // 16
    const int cols_full = n / TN;                // 128
    const int cols_new  = n_new / TN;            // 64
    const int slabs_tot = n / TM;                // 32
    const int tiles_new = slabs_new * cols_full; // 2048
    const int tiles_tot = tiles_new + (slabs_tot - slabs_new) * cols_new; // 3072

    const int G = gridDim.x;
    int t   = (int)((long long)blockIdx.x       * tiles_tot / G);
    int end = (int)((long long)(blockIdx.x + 1) * tiles_tot / G);

    const int role = (wid < 8) ? 0 : (wid < 12 ? 1 : 2);   // 0=cons,1=prod,2=issuer
    const int lt   = tid - 256;                  // producer-local tid (0..127)
    const int half = wid >> 2;                   // consumer A-half (0/1), wid<8
    const int srow = (wid & 3) * 32 + lane;      // consumer row within half

    int c = 0;                                   // global tile counter

    while (t < end) {
        // decode run: contiguous tiles sharing one double slab
        int slab, col0, slab_cols, slab_t0;
        if (t < tiles_new) {
            slab = t / cols_full; col0 = t - slab * cols_full;
            slab_cols = cols_full; slab_t0 = slab * cols_full;
        } else {
            int u = t - tiles_new;
            slab = slabs_new + u / cols_new; col0 = u % cols_new;
            slab_cols = cols_new;
            slab_t0 = tiles_new + (slab - slabs_new) * cols_new;
        }
        int run_len = slab_t0 + slab_cols - t;
        if (run_len > end - t) run_len = end - t;
        const int rowbase = slab * TM;
        const bool row_new = slab < slabs_new;

        // ---- run boundary: drain, load both A halves into SMEM ---------------
        __syncthreads();
        load_tileA(smem, SMEM_A(0), rowbase,       tid, NTHREADS);
        load_tileA(smem, SMEM_A(1), rowbase + 128, tid, NTHREADS);
        asm volatile("fence.proxy.async.shared::cta;" ::: "memory");
        __syncthreads();                         // A visible before any MMA

        if (role == 1) {
            // ==================== producer loop ====================
            for (int i = 0; i < run_len; ++i) {
                const int tt = c + i;
                const int sB = tt & 1;
                const int sT = tt & 3;
                const int colbase = (col0 + i) * TN;

                if (tt >= 2)
                    MBARRIER_WAIT_PARITY(sb + SMEM_EMPTY(sB),
                                         ((tt >> 1) & 1) ^ 1);

                load_tileB(smem, SMEM_B(sB), colbase, lt);
                if (lt < TN)
                    ((int*)(smem + SMEM_TCOL(sT)))[lt] = g_targ[colbase + lt];
                asm volatile("fence.proxy.async.shared::cta;" ::: "memory");
                MBARRIER_ARRIVE(sb + SMEM_READY(sT));
            }
        } else if (role == 2) {
            // ==================== issuer loop ====================
            TCGEN05_FENCE_AFTER();
            for (int i = 0; i < run_len; ++i) {
                const int tt = c + i;
                MBARRIER_WAIT_PARITY(sb + SMEM_READY(tt & 3), (tt >> 2) & 1);
                if (elect_one()) {
                    issue_mma_ss2(tmem + TMEM_D(tt & 1),
                                  sb + SMEM_A(0), sb + SMEM_A(1),
                                  sb + SMEM_B(tt & 1), sb + SMEM_FULL(tt & 1));
                }
            }
        } else {
            // ==================== consumer loop (short ring) ====================
            const int grow = rowbase + half * 128 + srow;
            const int ti = __ldg(&g_targ[grow]);
            float p = 0.0f, ng = 0.0f;

            for (int i = 0; i < run_len; ++i) {
                const int cc = c + i;
                const int sB = cc & 1;
                const int sT = cc & 3;

                MBARRIER_WAIT_PARITY(sb + SMEM_READY(sT), (cc >> 2) & 1);
                MBARRIER_WAIT_PARITY(sb + SMEM_FULL(sB),  (cc >> 1) & 1);
                TCGEN05_FENCE_AFTER();

                // both LDTMs issued before one wait (port pipelines them)
                const uint32_t dbase = tmem + TMEM_D(sB) + half * 64;
                uint32_t dr0[32], dr1[32];
                TCGEN05_LD_32X32B_X32(dr0, dbase);
                TCGEN05_LD_32X32B_X32(dr1, dbase + 32);
                TCGEN05_WAIT_LD();
                TCGEN05_FENCE_BEFORE();
                MBARRIER_ARRIVE(sb + SMEM_EMPTY(sB));   // D in regs; ring freed

                // mask processing now OFF the critical ring
                const int colbase = (col0 + i) * TN;
                const bool do_pos = row_new && (colbase < n_new);
                const int* tc = (const int*)(smem + SMEM_TCOL(sT));
                if (do_pos) {
                    #pragma unroll
                    for (int j = 0; j < 32; ++j) {
                        const float s0 = __uint_as_float(dr0[j]);
                        const int tj0 = tc[j];
                        if (ti != tj0) { if (s0 > MARGIN) ng += s0; }
                        else if (s0 < 1.0f - EPSV) p += 1.0f - s0;
                        const float s1 = __uint_as_float(dr1[j]);
                        const int tj1 = tc[32 + j];
                        if (ti != tj1) { if (s1 > MARGIN) ng += s1; }
                        else if (s1 < 1.0f - EPSV) p += 1.0f - s1;
                    }
                } else {
                    #pragma unroll
                    for (int j = 0; j < 32; ++j) {
                        const float s0 = __uint_as_float(dr0[j]);
                        if (ti != tc[j] && s0 > MARGIN) ng += s0;
                        const float s1 = __uint_as_float(dr1[j]);
                        if (ti != tc[32 + j] && s1 > MARGIN) ng += s1;
                    }
                }
            }

            atomicAdd(&g_neg[grow], ng);
            if (p != 0.0f) atomicAdd(&g_pos[grow], p);
        }

        c += run_len;
        t += run_len;
    }

    __syncthreads();
    if (wid == 0) TCGEN05_DEALLOC(tmem, TMEM_COLS);

    // ---- last CTA computes the final scalar ---------------------------------
    __threadfence();
    __shared__ int s_last;
    if (tid == 0)
        s_last = (atomicAdd(&g_done, 1) == gridDim.x - 1) ? 1 : 0;
    __syncthreads();
    if (s_last) {
        double* sh = reinterpret_cast<double*>(smem);
        const double a = (double)alpha;
        const double b = 1.0 - a;
        const double stale = (double)__ldcg(&g_pos[n_new - 1]);
        double s = 0.0;
        for (int i = tid; i < n; i += NTHREADS) {
            double pv = (i < n_new) ? (double)__ldcg(&g_pos[i]) : stale;
            s += a * pv + b * (double)__ldcg(&g_neg[i]);
        }
        sh[tid] = s;
        __syncthreads();
        for (int off = 256; off > 0; off >>= 1) {
            if (tid < off && tid + off < NTHREADS) sh[tid] += sh[tid + off];
            __syncthreads();
        }
        if (tid == 0) out[0] = (float)(sh[0] / (double)n);
    }
#endif  // HAS_TCGEN05
}

// ---------------------------------------------------------------------------
extern "C" void kernel_launch(void* const* d_in, const int* in_sizes, int n_in,
                              void* d_out, int out_size)
{
    const float* feat = (const float*)d_in[0];
    const void*  targ = d_in[1];

    const int n     = in_sizes[1];             // 8192
    const int d     = in_sizes[0] / n;         // 256
    const int n_new = in_sizes[2];             // 4096
    const int n_old = (n_in > 3) ? in_sizes[3] : 0;
    const float alpha = (n_old != 0) ? 0.9f : 0.5f;

    cudaFuncSetAttribute(sim_tc_kernel,
                         cudaFuncAttributeMaxDynamicSharedMemorySize, SMEM_TOTAL);

    {
        int total4 = (n * d) >> 2;
        convert_kernel<<<(total4 + 255) / 256, 256>>>(feat, targ, n, d);
    }
    sim_tc_kernel<<<GRID_CTAS, NTHREADS, SMEM_TOTAL>>>((float*)d_out, n, d, n_new, alpha);
}